// round 12
// baseline (speedup 1.0000x reference)
#include <cuda_runtime.h>
#include <cuda_bf16.h>
#include <math.h>
#include <stdint.h>

// ---------------------------------------------------------------------------
// Problem constants
// ---------------------------------------------------------------------------
#define VOCAB 32000
#define EDIM  1024
#define MDIM  4096
#define NLAY  4
#define BATCH 4
#define SEQ   2048
#define NROWS (BATCH*SEQ)   // 8192

// ---------------------------------------------------------------------------
// Static device scratch
// ---------------------------------------------------------------------------
__device__ __nv_bfloat16 g_hhi [NROWS * EDIM];
__device__ __nv_bfloat16 g_hlo [NROWS * EDIM];
__device__ __nv_bfloat16 g_qhi [NROWS * EDIM];
__device__ __nv_bfloat16 g_qlo [NROWS * EDIM];
__device__ __nv_bfloat16 g_khi [NROWS * EDIM];
__device__ __nv_bfloat16 g_klo [NROWS * EDIM];
__device__ float         g_v   [NROWS * EDIM];
__device__ __nv_bfloat16 g_vthi[(size_t)BATCH * EDIM * SEQ];
__device__ __nv_bfloat16 g_vtlo[(size_t)BATCH * EDIM * SEQ];
__device__ float         g_sc  [(size_t)BATCH * SEQ * SEQ];
__device__ __nv_bfloat16 g_whi [(size_t)BATCH * SEQ * SEQ];
__device__ __nv_bfloat16 g_wlo [(size_t)BATCH * SEQ * SEQ];
__device__ __nv_bfloat16 g_mhi [(size_t)NROWS * MDIM];
__device__ __nv_bfloat16 g_mlo [(size_t)NROWS * MDIM];
__device__ __nv_bfloat16 g_wqt [2 * EDIM * EDIM];
__device__ __nv_bfloat16 g_wkt [2 * EDIM * EDIM];
__device__ __nv_bfloat16 g_wvt [2 * EDIM * EDIM];
__device__ __nv_bfloat16 g_w1t [(size_t)2 * NLAY * MDIM * EDIM];
__device__ __nv_bfloat16 g_w2t [(size_t)2 * NLAY * EDIM * MDIM];

// ---------------------------------------------------------------------------
// PTX helpers (valid at plain compute_103 target)
// ---------------------------------------------------------------------------
#define CP_ASYNC16(dst, src) \
    asm volatile("cp.async.cg.shared.global [%0], [%1], 16;" :: "r"(dst), "l"(src))
#define CP_COMMIT() asm volatile("cp.async.commit_group;" ::: "memory")
#define CP_WAIT(n)  asm volatile("cp.async.wait_group %0;" :: "n"(n) : "memory")

__device__ __forceinline__ uint32_t smem_u32(const void* p) {
    uint32_t a;
    asm("{ .reg .u64 t; cvta.to.shared.u64 t, %1; cvt.u32.u64 %0, t; }"
        : "=r"(a) : "l"(p));
    return a;
}

#define LDSM4(R, A) \
    asm volatile("ldmatrix.sync.aligned.m8n8.x4.shared.b16 {%0,%1,%2,%3}, [%4];" \
        : "=r"((R)[0]), "=r"((R)[1]), "=r"((R)[2]), "=r"((R)[3]) : "r"(A))

__device__ __forceinline__ void mma16816(float* c, const uint32_t* a, const uint32_t* b) {
    asm volatile(
        "mma.sync.aligned.m16n8k16.row.col.f32.bf16.bf16.f32 "
        "{%0,%1,%2,%3}, {%4,%5,%6,%7}, {%8,%9}, {%0,%1,%2,%3};"
        : "+f"(c[0]), "+f"(c[1]), "+f"(c[2]), "+f"(c[3])
        : "r"(a[0]), "r"(a[1]), "r"(a[2]), "r"(a[3]), "r"(b[0]), "r"(b[1]));
}

__device__ __forceinline__ void split2(float v, __nv_bfloat16& hi, __nv_bfloat16& lo) {
    hi = __float2bfloat16(v);
    lo = __float2bfloat16(v - __bfloat162float(hi));
}

// ---------------------------------------------------------------------------
// HMMA GEMM (round-6 champion): out = act(scale*(Ahi+Alo)(Bhi+Blo)^T + bias)
//   A [M,K] K-major, B [N,K] K-major. CTA tile 128x256, 8 warps (64x64 each),
//   BK=64, 2-stage cp.async pipeline, interleaved LDSM, pass-major MMA order.
// ---------------------------------------------------------------------------
struct GP {
    const __nv_bfloat16 *Ahi, *Alo, *Bhi, *Blo;
    const float* bias;
    float* outF;
    __nv_bfloat16 *outHi, *outLo;
    int K, ldA, ldB, ldC;
    size_t szA, szB, szC;
    float scale;
    int relu;
    int maskSkip;
    int triK;
};

#define BK      64
#define APITCH  72
#define TILEA   (128*APITCH*2)
#define TILEBB  (256*APITCH*2)
#define STGB    (2*TILEA + 2*TILEBB)
#define NSTG    2
#define GEMM_SMEM (NSTG*STGB)      // 221184

#define OFF_AHI 0
#define OFF_ALO (TILEA)
#define OFF_BHI (2*TILEA)
#define OFF_BLO (2*TILEA + TILEBB)

__global__ void __launch_bounds__(256, 1) tgemm(GP p)
{
    const int m0 = blockIdx.y * 128;
    const int n0 = blockIdx.x * 256;
    if (p.maskSkip && (n0 + 256 <= m0)) return;

    extern __shared__ char smem[];
    const uint32_t sbase = smem_u32(smem);

    const int tid  = threadIdx.x;
    const int wid  = tid >> 5;
    const int lane = tid & 31;
    const int g    = lane >> 2;
    const int tg   = lane & 3;
    const int wm0 = (wid & 1) * 64;
    const int wn0 = (wid >> 1) * 64;

    const size_t zA = (size_t)blockIdx.z * p.szA;
    const size_t zB = (size_t)blockIdx.z * p.szB;
    const size_t zC = (size_t)blockIdx.z * p.szC;

    const char* aHi = (const char*)(p.Ahi + zA + (size_t)m0 * p.ldA);
    const char* aLo = (const char*)(p.Alo + zA + (size_t)m0 * p.ldA);
    const char* bHi = (const char*)(p.Bhi + zB + (size_t)n0 * p.ldB);
    const char* bLo = (const char*)(p.Blo + zB + (size_t)n0 * p.ldB);
    const size_t rsA = (size_t)p.ldA * 2;
    const size_t rsB = (size_t)p.ldB * 2;

    const int l15 = lane & 15;
    const uint32_t aoff = (uint32_t)(((wm0 + l15) * APITCH + ((lane >> 4) * 8)) * 2);
    const int bN  = ((lane & 16) >> 1) + (lane & 7);
    const uint32_t boff = (uint32_t)(((wn0 + bN) * APITCH + (lane & 8)) * 2);

    const int r0c = tid >> 3;
    const int ccc = (tid & 7) * 16;

    const int NC = p.K / BK;
    const int c0 = p.triK ? (m0 / BK) : 0;
    const int NCr = NC - c0;

    auto load_chunk = [&](int c, int stg) {
        const size_t kb = (size_t)c * BK * 2;
        const uint32_t sb = sbase + stg * STGB;
        #pragma unroll
        for (int h = 0; h < 4; h++) {
            const int row = r0c + h * 32;
            const uint32_t doff = row * (APITCH*2) + ccc;
            const size_t goA = (size_t)row * rsA + kb + ccc;
            CP_ASYNC16(sb + OFF_AHI + doff, aHi + goA);
            CP_ASYNC16(sb + OFF_ALO + doff, aLo + goA);
        }
        #pragma unroll
        for (int h = 0; h < 8; h++) {
            const int row = r0c + h * 32;
            const uint32_t doff = row * (APITCH*2) + ccc;
            const size_t goB = (size_t)row * rsB + kb + ccc;
            CP_ASYNC16(sb + OFF_BHI + doff, bHi + goB);
            CP_ASYNC16(sb + OFF_BLO + doff, bLo + goB);
        }
        CP_COMMIT();
    };

    float acc[4][8][4];
    #pragma unroll
    for (int a = 0; a < 4; a++)
        #pragma unroll
        for (int b = 0; b < 8; b++)
            #pragma unroll
            for (int q = 0; q < 4; q++) acc[a][b][q] = 0.f;

    load_chunk(c0 + 0, 0);
    load_chunk(c0 + 1, 1);

    for (int cr = 0; cr < NCr; cr++) {
        const int stg = cr & 1;
        if (cr + 1 < NCr) CP_WAIT(1);
        else              CP_WAIT(0);
        __syncthreads();

        const uint32_t sb = sbase + stg * STGB;
        #pragma unroll
        for (int kk = 0; kk < BK; kk += 16) {
            uint32_t ah[4][4], al[4][4];
            #pragma unroll
            for (int mt = 0; mt < 4; mt++) {
                const uint32_t ao = sb + aoff + mt*(16*APITCH*2) + kk*2;
                LDSM4(ah[mt], ao);
                LDSM4(al[mt], ao + TILEA);
            }
            #pragma unroll
            for (int ntp = 0; ntp < 4; ntp++) {
                uint32_t bh[4], bl[4];
                const uint32_t bo = sb + OFF_BHI + boff + ntp*(16*APITCH*2) + kk*2;
                LDSM4(bh, bo);
                LDSM4(bl, bo + TILEBB);
                #pragma unroll
                for (int mt = 0; mt < 4; mt++)
                    #pragma unroll
                    for (int nt = 0; nt < 2; nt++)
                        mma16816(acc[mt][ntp*2+nt], ah[mt], &bh[nt*2]);
                #pragma unroll
                for (int mt = 0; mt < 4; mt++)
                    #pragma unroll
                    for (int nt = 0; nt < 2; nt++)
                        mma16816(acc[mt][ntp*2+nt], ah[mt], &bl[nt*2]);
                #pragma unroll
                for (int mt = 0; mt < 4; mt++)
                    #pragma unroll
                    for (int nt = 0; nt < 2; nt++)
                        mma16816(acc[mt][ntp*2+nt], al[mt], &bh[nt*2]);
            }
        }

        __syncthreads();
        if (cr + NSTG < NCr) load_chunk(c0 + cr + NSTG, stg);
    }

    float2 bb[8];
    #pragma unroll
    for (int nt = 0; nt < 8; nt++) {
        if (p.bias) bb[nt] = *(const float2*)(p.bias + n0 + wn0 + nt*8 + tg*2);
        else        bb[nt] = make_float2(0.f, 0.f);
    }
    #pragma unroll
    for (int mt = 0; mt < 4; mt++) {
        #pragma unroll
        for (int half = 0; half < 2; half++) {
            const int r = m0 + wm0 + mt*16 + g + half*8;
            #pragma unroll
            for (int nt = 0; nt < 8; nt++) {
                float x0 = acc[mt][nt][half*2+0] * p.scale + bb[nt].x;
                float x1 = acc[mt][nt][half*2+1] * p.scale + bb[nt].y;
                if (p.relu) { x0 = fmaxf(x0, 0.f); x1 = fmaxf(x1, 0.f); }
                const int cc = n0 + wn0 + nt*8 + tg*2;
                const size_t o = zC + (size_t)r * p.ldC + cc;
                if (p.outF)
                    *(float2*)(p.outF + o) = make_float2(x0, x1);
                if (p.outHi) {
                    __nv_bfloat16 h0, l0, h1, l1;
                    split2(x0, h0, l0);
                    split2(x1, h1, l1);
                    uint32_t hp = (uint32_t)__bfloat16_as_ushort(h0) |
                                  ((uint32_t)__bfloat16_as_ushort(h1) << 16);
                    uint32_t lp = (uint32_t)__bfloat16_as_ushort(l0) |
                                  ((uint32_t)__bfloat16_as_ushort(l1) << 16);
                    *(uint32_t*)(p.outHi + o) = hp;
                    *(uint32_t*)(p.outLo + o) = lp;
                }
            }
        }
    }
}

// ---------------------------------------------------------------------------
// Embedding gather + hi/lo split
// ---------------------------------------------------------------------------
__global__ void embed_split(const int* __restrict__ x, const float* __restrict__ emb,
                            __nv_bfloat16* __restrict__ hhi, __nv_bfloat16* __restrict__ hlo)
{
    const int r = blockIdx.x;
    const int row = x[r];
    const float4 f = ((const float4*)(emb + (size_t)row * EDIM))[threadIdx.x];
    const size_t o = (size_t)r * EDIM + threadIdx.x * 4;
    __nv_bfloat16 h, l;
    split2(f.x, h, l); hhi[o+0] = h; hlo[o+0] = l;
    split2(f.y, h, l); hhi[o+1] = h; hlo[o+1] = l;
    split2(f.z, h, l); hhi[o+2] = h; hlo[o+2] = l;
    split2(f.w, h, l); hhi[o+3] = h; hlo[o+3] = l;
}

// ---------------------------------------------------------------------------
// Transpose + hi/lo split: src fp32 [R,C] -> dst bf16 [C,R] (hi,lo)
// ---------------------------------------------------------------------------
__global__ void transpose_split(const float* __restrict__ src,
                                __nv_bfloat16* __restrict__ dhi,
                                __nv_bfloat16* __restrict__ dlo,
                                int R, int C, size_t szSrc, size_t szDst)
{
    __shared__ float t[32][33];
    src += (size_t)blockIdx.z * szSrc;
    dhi += (size_t)blockIdx.z * szDst;
    dlo += (size_t)blockIdx.z * szDst;
    const int c0 = blockIdx.x * 32, r0 = blockIdx.y * 32;
    const int tx = threadIdx.x, ty = threadIdx.y;
    #pragma unroll
    for (int j = 0; j < 4; j++)
        t[ty + j*8][tx] = src[(size_t)(r0 + ty + j*8) * C + c0 + tx];
    __syncthreads();
    #pragma unroll
    for (int j = 0; j < 4; j++) {
        const float v = t[tx][ty + j*8];
        __nv_bfloat16 h, l;
        split2(v, h, l);
        const size_t o = (size_t)(c0 + ty + j*8) * R + r0 + tx;
        dhi[o] = h; dlo[o] = l;
    }
}

// ---------------------------------------------------------------------------
// Masked softmax (keep t >= s), fp32 in -> bf16 hi/lo out, exp cached in regs
// ---------------------------------------------------------------------------
__global__ void __launch_bounds__(256) softmax_split(const float* __restrict__ sc,
                                                     __nv_bfloat16* __restrict__ whi,
                                                     __nv_bfloat16* __restrict__ wlo)
{
    const int s = blockIdx.x, b = blockIdx.y;
    const size_t base = ((size_t)b * SEQ + s) * SEQ;
    const float* row = sc + base;
    const int tid = threadIdx.x;
    __shared__ float red[256];

    float m = -1e30f;
    for (int t = s + tid; t < SEQ; t += 256) m = fmaxf(m, row[t]);
    red[tid] = m; __syncthreads();
    #pragma unroll
    for (int o = 128; o > 0; o >>= 1) {
        if (tid < o) red[tid] = fmaxf(red[tid], red[tid + o]);
        __syncthreads();
    }
    m = red[0]; __syncthreads();

    float ev[8];
    float sum = 0.f;
    {
        int j = 0;
        for (int t = s + tid; t < SEQ; t += 256, j++) {
            const float e = expf(row[t] - m);
            ev[j] = e;
            sum += e;
        }
    }
    red[tid] = sum; __syncthreads();
    #pragma unroll
    for (int o = 128; o > 0; o >>= 1) {
        if (tid < o) red[tid] += red[tid + o];
        __syncthreads();
    }
    const float inv = 1.f / red[0];

    for (int t = tid; t < s; t += 256) {
        whi[base + t] = __float2bfloat16(0.f);
        wlo[base + t] = __float2bfloat16(0.f);
    }
    {
        int j = 0;
        for (int t = s + tid; t < SEQ; t += 256, j++) {
            __nv_bfloat16 h, l;
            split2(ev[j] * inv, h, l);
            whi[base + t] = h;
            wlo[base + t] = l;
        }
    }
}

// ---------------------------------------------------------------------------
// Host
// ---------------------------------------------------------------------------
template <typename T>
static T* sym(const void* s) { void* p = nullptr; cudaGetSymbolAddress(&p, s); return (T*)p; }

static void launch_gemm(GP& p, int M, int N, int Z, cudaStream_t st)
{
    dim3 g(N / 256, M / 128, Z);
    tgemm<<<g, 256, GEMM_SMEM, st>>>(p);
}

extern "C" void kernel_launch(void* const* d_in, const int* in_sizes, int n_in,
                              void* d_out, int out_size)
{
    const int*   x   = (const int*)  d_in[0];
    const float* emb = (const float*)d_in[1];
    const float* Wq  = (const float*)d_in[2];
    const float* bq  = (const float*)d_in[3];
    const float* Wk  = (const float*)d_in[4];
    const float* bk  = (const float*)d_in[5];
    const float* Wv  = (const float*)d_in[6];
    const float* bv  = (const float*)d_in[7];
    const float* W1  = (const float*)d_in[8];
    const float* b1  = (const float*)d_in[9];
    const float* W2  = (const float*)d_in[10];
    const float* b2  = (const float*)d_in[11];
    float* out = (float*)d_out;

    // one-time resources (created on the uncaptured correctness call)
    static cudaStream_t s1 = nullptr, s2 = nullptr, s3 = nullptr;
    static cudaEvent_t ev0 = nullptr, evW = nullptr, evQKV = nullptr;
    static cudaEvent_t evA[2] = {nullptr, nullptr};
    if (!s1) {
        cudaFuncSetAttribute(tgemm, cudaFuncAttributeMaxDynamicSharedMemorySize, GEMM_SMEM);
        cudaStreamCreateWithFlags(&s1, cudaStreamNonBlocking);
        cudaStreamCreateWithFlags(&s2, cudaStreamNonBlocking);
        cudaStreamCreateWithFlags(&s3, cudaStreamNonBlocking);
        cudaEventCreateWithFlags(&ev0, cudaEventDisableTiming);
        cudaEventCreateWithFlags(&evW, cudaEventDisableTiming);
        cudaEventCreateWithFlags(&evQKV, cudaEventDisableTiming);
        cudaEventCreateWithFlags(&evA[0], cudaEventDisableTiming);
        cudaEventCreateWithFlags(&evA[1], cudaEventDisableTiming);
    }

    __nv_bfloat16* hhi = sym<__nv_bfloat16>(g_hhi);
    __nv_bfloat16* hlo = sym<__nv_bfloat16>(g_hlo);
    __nv_bfloat16* qhi = sym<__nv_bfloat16>(g_qhi);
    __nv_bfloat16* qlo = sym<__nv_bfloat16>(g_qlo);
    __nv_bfloat16* khi = sym<__nv_bfloat16>(g_khi);
    __nv_bfloat16* klo = sym<__nv_bfloat16>(g_klo);
    float*         v   = sym<float>(g_v);
    __nv_bfloat16* vthi= sym<__nv_bfloat16>(g_vthi);
    __nv_bfloat16* vtlo= sym<__nv_bfloat16>(g_vtlo);
    float*         sc  = sym<float>(g_sc);
    __nv_bfloat16* whi = sym<__nv_bfloat16>(g_whi);
    __nv_bfloat16* wlo = sym<__nv_bfloat16>(g_wlo);
    __nv_bfloat16* mhi = sym<__nv_bfloat16>(g_mhi);
    __nv_bfloat16* mlo = sym<__nv_bfloat16>(g_mlo);
    __nv_bfloat16* wqt = sym<__nv_bfloat16>(g_wqt);
    __nv_bfloat16* wkt = sym<__nv_bfloat16>(g_wkt);
    __nv_bfloat16* wvt = sym<__nv_bfloat16>(g_wvt);
    __nv_bfloat16* w1t = sym<__nv_bfloat16>(g_w1t);
    __nv_bfloat16* w2t = sym<__nv_bfloat16>(g_w2t);

    const size_t EE = (size_t)EDIM * EDIM;
    const size_t EM = (size_t)EDIM * MDIM;
    const size_t SE = (size_t)SEQ * EDIM;
    const size_t SS = (size_t)SEQ * SEQ;
    const cudaStream_t s0 = 0;

    dim3 tb(32, 8);

    // fork s3: W1/W2 transposes overlap the attention phase
    cudaEventRecord(ev0, s0);
    cudaStreamWaitEvent(s3, ev0, 0);
    transpose_split<<<dim3(MDIM/32, EDIM/32, NLAY), tb, 0, s3>>>(W1, w1t, w1t + (size_t)NLAY*EM, EDIM, MDIM, EM, EM);
    transpose_split<<<dim3(EDIM/32, MDIM/32, NLAY), tb, 0, s3>>>(W2, w2t, w2t + (size_t)NLAY*EM, MDIM, EDIM, EM, EM);
    cudaEventRecord(evW, s3);

    // main stream: QKV weight transposes + embedding + QKV GEMMs
    transpose_split<<<dim3(EDIM/32, EDIM/32, 1), tb, 0, s0>>>(Wq, wqt, wqt + EE, EDIM, EDIM, 0, 0);
    transpose_split<<<dim3(EDIM/32, EDIM/32, 1), tb, 0, s0>>>(Wk, wkt, wkt + EE, EDIM, EDIM, 0, 0);
    transpose_split<<<dim3(EDIM/32, EDIM/32, 1), tb, 0, s0>>>(Wv, wvt, wvt + EE, EDIM, EDIM, 0, 0);
    embed_split<<<NROWS, 256, 0, s0>>>(x, emb, hhi, hlo);

    GP p = {};
    p.Ahi = hhi; p.Alo = hlo; p.ldA = EDIM; p.ldB = EDIM; p.ldC = EDIM;
    p.K = EDIM; p.scale = 1.f; p.relu = 0; p.maskSkip = 0; p.triK = 0;
    p.szA = p.szB = p.szC = 0;

    p.Bhi = wqt; p.Blo = wqt + EE; p.bias = bq;
    p.outHi = qhi; p.outLo = qlo; p.outF = nullptr;
    launch_gemm(p, NROWS, EDIM, 1, s0);

    p.Bhi = wkt; p.Blo = wkt + EE; p.bias = bk;
    p.outHi = khi; p.outLo = klo;
    launch_gemm(p, NROWS, EDIM, 1, s0);

    p.Bhi = wvt; p.Blo = wvt + EE; p.bias = bv;
    p.outHi = nullptr; p.outLo = nullptr; p.outF = v;
    launch_gemm(p, NROWS, EDIM, 1, s0);
    cudaEventRecord(evQKV, s0);

    // ---- attention, per-batch chains interleaved on two streams ----
    cudaStreamWaitEvent(s1, evQKV, 0);
    cudaStreamWaitEvent(s2, evQKV, 0);
    cudaStream_t abs_[2] = {s1, s2};

    for (int b = 0; b < BATCH; b++) {
        cudaStream_t st = abs_[b & 1];

        // vT(b): [SEQ,EDIM] fp32 -> [EDIM,SEQ] bf16 hi/lo
        transpose_split<<<dim3(EDIM/32, SEQ/32, 1), tb, 0, st>>>(
            v + (size_t)b * SE, vthi + (size_t)b * (size_t)EDIM * SEQ,
            vtlo + (size_t)b * (size_t)EDIM * SEQ, SEQ, EDIM, 0, 0);

        // scores(b) = scale * q k^T, masked-tile skip
        GP ps = p;
        ps.Ahi = qhi + (size_t)b * SE; ps.Alo = qlo + (size_t)b * SE;
        ps.Bhi = khi + (size_t)b * SE; ps.Blo = klo + (size_t)b * SE;
        ps.ldA = EDIM; ps.ldB = EDIM; ps.ldC = SEQ; ps.K = EDIM;
        ps.szA = ps.szB = ps.szC = 0;
        ps.bias = nullptr; ps.outF = sc + (size_t)b * SS;
        ps.outHi = nullptr; ps.outLo = nullptr;
        ps.scale = 1.f / 32.f; ps.relu = 0; ps.maskSkip = 1; ps.triK = 0;
        launch_gemm(ps, SEQ, SEQ, 1, st);

        // softmax(b)
        softmax_split<<<dim3(SEQ, 1), 256, 0, st>>>(
            sc + (size_t)b * SS, whi + (size_t)b * SS, wlo + (size_t)b * SS);

        // h(b) = relu(w v), triangular K skip
        GP pw = p;
        pw.Ahi = whi + (size_t)b * SS; pw.Alo = wlo + (size_t)b * SS;
        pw.Bhi = vthi + (size_t)b * (size_t)EDIM * SEQ;
        pw.Blo = vtlo + (size_t)b * (size_t)EDIM * SEQ;
        pw.ldA = SEQ; pw.ldB = SEQ; pw.ldC = EDIM; pw.K = SEQ;
        pw.szA = pw.szB = pw.szC = 0;
        pw.bias = nullptr; pw.outF = nullptr;
        pw.outHi = hhi + (size_t)b * SE; pw.outLo = hlo + (size_t)b * SE;
        pw.scale = 1.f; pw.relu = 1; pw.maskSkip = 0; pw.triK = 1;
        launch_gemm(pw, SEQ, EDIM, 1, st);
    }
    cudaEventRecord(evA[0], s1);
    cudaEventRecord(evA[1], s2);

    // join before MLP
    cudaStreamWaitEvent(s0, evA[0], 0);
    cudaStreamWaitEvent(s0, evA[1], 0);
    cudaStreamWaitEvent(s0, evW, 0);

    // ---- MLP stack ----
    p.szA = p.szB = p.szC = 0;
    p.maskSkip = 0; p.triK = 0;
    __nv_bfloat16 *curHi = hhi, *curLo = hlo;
    __nv_bfloat16 *altHi = qhi, *altLo = qlo;
    for (int i = 0; i < NLAY; i++) {
        p.Ahi = curHi; p.Alo = curLo;
        p.Bhi = w1t + (size_t)i * EM; p.Blo = w1t + (size_t)(NLAY + i) * EM;
        p.ldA = EDIM; p.ldB = EDIM; p.ldC = MDIM; p.K = EDIM;
        p.bias = b1 + (size_t)i * MDIM;
        p.outHi = mhi; p.outLo = mlo; p.outF = nullptr;
        p.scale = 1.f; p.relu = 1;
        launch_gemm(p, NROWS, MDIM, 1, s0);

        p.Ahi = mhi; p.Alo = mlo;
        p.Bhi = w2t + (size_t)i * EM; p.Blo = w2t + (size_t)(NLAY + i) * EM;
        p.ldA = MDIM; p.ldB = MDIM; p.ldC = EDIM; p.K = MDIM;
        p.bias = b2 + (size_t)i * EDIM;
        if (i == NLAY - 1) {
            p.outHi = nullptr; p.outLo = nullptr; p.outF = out;
        } else {
            p.outHi = altHi; p.outLo = altLo; p.outF = nullptr;
        }
        launch_gemm(p, NROWS, EDIM, 1, s0);

        __nv_bfloat16* t;
        t = curHi; curHi = altHi; altHi = t;
        t = curLo; curLo = altLo; altLo = t;
    }
}

// round 13
// speedup vs baseline: 1.0167x; 1.0167x over previous
#include <cuda_runtime.h>
#include <cuda_bf16.h>
#include <math.h>
#include <stdint.h>

// ---------------------------------------------------------------------------
// Problem constants
// ---------------------------------------------------------------------------
#define VOCAB 32000
#define EDIM  1024
#define MDIM  4096
#define NLAY  4
#define BATCH 4
#define SEQ   2048
#define NROWS (BATCH*SEQ)   // 8192

// ---------------------------------------------------------------------------
// Static device scratch
// ---------------------------------------------------------------------------
__device__ __nv_bfloat16 g_hhi [NROWS * EDIM];
__device__ __nv_bfloat16 g_hlo [NROWS * EDIM];
__device__ __nv_bfloat16 g_qhi [NROWS * EDIM];
__device__ __nv_bfloat16 g_qlo [NROWS * EDIM];
__device__ __nv_bfloat16 g_khi [NROWS * EDIM];
__device__ __nv_bfloat16 g_klo [NROWS * EDIM];
__device__ __nv_bfloat16 g_vhl [(size_t)2 * NROWS * EDIM];   // [hi | lo]
__device__ __nv_bfloat16 g_vthi[(size_t)BATCH * EDIM * SEQ];
__device__ __nv_bfloat16 g_vtlo[(size_t)BATCH * EDIM * SEQ];
__device__ float         g_sc  [(size_t)BATCH * SEQ * SEQ];
__device__ __nv_bfloat16 g_whi [(size_t)BATCH * SEQ * SEQ];
__device__ __nv_bfloat16 g_wlo [(size_t)BATCH * SEQ * SEQ];
__device__ __nv_bfloat16 g_mhi [(size_t)NROWS * MDIM];
__device__ __nv_bfloat16 g_mlo [(size_t)NROWS * MDIM];
__device__ __nv_bfloat16 g_wqt [2 * EDIM * EDIM];
__device__ __nv_bfloat16 g_wkt [2 * EDIM * EDIM];
__device__ __nv_bfloat16 g_wvt [2 * EDIM * EDIM];
__device__ __nv_bfloat16 g_w1t [(size_t)2 * NLAY * MDIM * EDIM];
__device__ __nv_bfloat16 g_w2t [(size_t)2 * NLAY * EDIM * MDIM];

// ---------------------------------------------------------------------------
// PTX helpers (valid at plain compute_103 target)
// ---------------------------------------------------------------------------
#define CP_ASYNC16(dst, src) \
    asm volatile("cp.async.cg.shared.global [%0], [%1], 16;" :: "r"(dst), "l"(src))
#define CP_COMMIT() asm volatile("cp.async.commit_group;" ::: "memory")
#define CP_WAIT(n)  asm volatile("cp.async.wait_group %0;" :: "n"(n) : "memory")

__device__ __forceinline__ uint32_t smem_u32(const void* p) {
    uint32_t a;
    asm("{ .reg .u64 t; cvta.to.shared.u64 t, %1; cvt.u32.u64 %0, t; }"
        : "=r"(a) : "l"(p));
    return a;
}

#define LDSM4(R, A) \
    asm volatile("ldmatrix.sync.aligned.m8n8.x4.shared.b16 {%0,%1,%2,%3}, [%4];" \
        : "=r"((R)[0]), "=r"((R)[1]), "=r"((R)[2]), "=r"((R)[3]) : "r"(A))

__device__ __forceinline__ void mma16816(float* c, const uint32_t* a, const uint32_t* b) {
    asm volatile(
        "mma.sync.aligned.m16n8k16.row.col.f32.bf16.bf16.f32 "
        "{%0,%1,%2,%3}, {%4,%5,%6,%7}, {%8,%9}, {%0,%1,%2,%3};"
        : "+f"(c[0]), "+f"(c[1]), "+f"(c[2]), "+f"(c[3])
        : "r"(a[0]), "r"(a[1]), "r"(a[2]), "r"(a[3]), "r"(b[0]), "r"(b[1]));
}

__device__ __forceinline__ void split2(float v, __nv_bfloat16& hi, __nv_bfloat16& lo) {
    hi = __float2bfloat16(v);
    lo = __float2bfloat16(v - __bfloat162float(hi));
}

// ---------------------------------------------------------------------------
// HMMA GEMM (round-6 champion): out = act(scale*(Ahi+Alo)(Bhi+Blo)^T + bias)
//   A [M,K] K-major, B [N,K] K-major. CTA tile 128x256, 8 warps (64x64 each),
//   BK=64, 2-stage cp.async pipeline, interleaved LDSM, pass-major MMA order.
// ---------------------------------------------------------------------------
struct GP {
    const __nv_bfloat16 *Ahi, *Alo, *Bhi, *Blo;
    const float* bias;
    float* outF;
    __nv_bfloat16 *outHi, *outLo;
    int K, ldA, ldB, ldC;
    size_t szA, szB, szC;
    float scale;
    int relu;
    int maskSkip;
    int triK;
};

#define BK      64
#define APITCH  72
#define TILEA   (128*APITCH*2)
#define TILEBB  (256*APITCH*2)
#define STGB    (2*TILEA + 2*TILEBB)
#define NSTG    2
#define GEMM_SMEM (NSTG*STGB)      // 221184

#define OFF_AHI 0
#define OFF_ALO (TILEA)
#define OFF_BHI (2*TILEA)
#define OFF_BLO (2*TILEA + TILEBB)

__global__ void __launch_bounds__(256, 1) tgemm(GP p)
{
    const int m0 = blockIdx.y * 128;
    const int n0 = blockIdx.x * 256;
    if (p.maskSkip && (n0 + 256 <= m0)) return;

    extern __shared__ char smem[];
    const uint32_t sbase = smem_u32(smem);

    const int tid  = threadIdx.x;
    const int wid  = tid >> 5;
    const int lane = tid & 31;
    const int g    = lane >> 2;
    const int tg   = lane & 3;
    const int wm0 = (wid & 1) * 64;
    const int wn0 = (wid >> 1) * 64;

    const size_t zA = (size_t)blockIdx.z * p.szA;
    const size_t zB = (size_t)blockIdx.z * p.szB;
    const size_t zC = (size_t)blockIdx.z * p.szC;

    const char* aHi = (const char*)(p.Ahi + zA + (size_t)m0 * p.ldA);
    const char* aLo = (const char*)(p.Alo + zA + (size_t)m0 * p.ldA);
    const char* bHi = (const char*)(p.Bhi + zB + (size_t)n0 * p.ldB);
    const char* bLo = (const char*)(p.Blo + zB + (size_t)n0 * p.ldB);
    const size_t rsA = (size_t)p.ldA * 2;
    const size_t rsB = (size_t)p.ldB * 2;

    const int l15 = lane & 15;
    const uint32_t aoff = (uint32_t)(((wm0 + l15) * APITCH + ((lane >> 4) * 8)) * 2);
    const int bN  = ((lane & 16) >> 1) + (lane & 7);
    const uint32_t boff = (uint32_t)(((wn0 + bN) * APITCH + (lane & 8)) * 2);

    const int r0c = tid >> 3;
    const int ccc = (tid & 7) * 16;

    const int NC = p.K / BK;
    const int c0 = p.triK ? (m0 / BK) : 0;
    const int NCr = NC - c0;

    auto load_chunk = [&](int c, int stg) {
        const size_t kb = (size_t)c * BK * 2;
        const uint32_t sb = sbase + stg * STGB;
        #pragma unroll
        for (int h = 0; h < 4; h++) {
            const int row = r0c + h * 32;
            const uint32_t doff = row * (APITCH*2) + ccc;
            const size_t goA = (size_t)row * rsA + kb + ccc;
            CP_ASYNC16(sb + OFF_AHI + doff, aHi + goA);
            CP_ASYNC16(sb + OFF_ALO + doff, aLo + goA);
        }
        #pragma unroll
        for (int h = 0; h < 8; h++) {
            const int row = r0c + h * 32;
            const uint32_t doff = row * (APITCH*2) + ccc;
            const size_t goB = (size_t)row * rsB + kb + ccc;
            CP_ASYNC16(sb + OFF_BHI + doff, bHi + goB);
            CP_ASYNC16(sb + OFF_BLO + doff, bLo + goB);
        }
        CP_COMMIT();
    };

    float acc[4][8][4];
    #pragma unroll
    for (int a = 0; a < 4; a++)
        #pragma unroll
        for (int b = 0; b < 8; b++)
            #pragma unroll
            for (int q = 0; q < 4; q++) acc[a][b][q] = 0.f;

    load_chunk(c0 + 0, 0);
    load_chunk(c0 + 1, 1);

    for (int cr = 0; cr < NCr; cr++) {
        const int stg = cr & 1;
        if (cr + 1 < NCr) CP_WAIT(1);
        else              CP_WAIT(0);
        __syncthreads();

        const uint32_t sb = sbase + stg * STGB;
        #pragma unroll
        for (int kk = 0; kk < BK; kk += 16) {
            uint32_t ah[4][4], al[4][4];
            #pragma unroll
            for (int mt = 0; mt < 4; mt++) {
                const uint32_t ao = sb + aoff + mt*(16*APITCH*2) + kk*2;
                LDSM4(ah[mt], ao);
                LDSM4(al[mt], ao + TILEA);
            }
            #pragma unroll
            for (int ntp = 0; ntp < 4; ntp++) {
                uint32_t bh[4], bl[4];
                const uint32_t bo = sb + OFF_BHI + boff + ntp*(16*APITCH*2) + kk*2;
                LDSM4(bh, bo);
                LDSM4(bl, bo + TILEBB);
                #pragma unroll
                for (int mt = 0; mt < 4; mt++)
                    #pragma unroll
                    for (int nt = 0; nt < 2; nt++)
                        mma16816(acc[mt][ntp*2+nt], ah[mt], &bh[nt*2]);
                #pragma unroll
                for (int mt = 0; mt < 4; mt++)
                    #pragma unroll
                    for (int nt = 0; nt < 2; nt++)
                        mma16816(acc[mt][ntp*2+nt], ah[mt], &bl[nt*2]);
                #pragma unroll
                for (int mt = 0; mt < 4; mt++)
                    #pragma unroll
                    for (int nt = 0; nt < 2; nt++)
                        mma16816(acc[mt][ntp*2+nt], al[mt], &bh[nt*2]);
            }
        }

        __syncthreads();
        if (cr + NSTG < NCr) load_chunk(c0 + cr + NSTG, stg);
    }

    float2 bb[8];
    #pragma unroll
    for (int nt = 0; nt < 8; nt++) {
        if (p.bias) bb[nt] = *(const float2*)(p.bias + n0 + wn0 + nt*8 + tg*2);
        else        bb[nt] = make_float2(0.f, 0.f);
    }
    #pragma unroll
    for (int mt = 0; mt < 4; mt++) {
        #pragma unroll
        for (int half = 0; half < 2; half++) {
            const int r = m0 + wm0 + mt*16 + g + half*8;
            #pragma unroll
            for (int nt = 0; nt < 8; nt++) {
                float x0 = acc[mt][nt][half*2+0] * p.scale + bb[nt].x;
                float x1 = acc[mt][nt][half*2+1] * p.scale + bb[nt].y;
                if (p.relu) { x0 = fmaxf(x0, 0.f); x1 = fmaxf(x1, 0.f); }
                const int cc = n0 + wn0 + nt*8 + tg*2;
                const size_t o = zC + (size_t)r * p.ldC + cc;
                if (p.outF)
                    *(float2*)(p.outF + o) = make_float2(x0, x1);
                if (p.outHi) {
                    __nv_bfloat16 h0, l0, h1, l1;
                    split2(x0, h0, l0);
                    split2(x1, h1, l1);
                    uint32_t hp = (uint32_t)__bfloat16_as_ushort(h0) |
                                  ((uint32_t)__bfloat16_as_ushort(h1) << 16);
                    uint32_t lp = (uint32_t)__bfloat16_as_ushort(l0) |
                                  ((uint32_t)__bfloat16_as_ushort(l1) << 16);
                    *(uint32_t*)(p.outHi + o) = hp;
                    *(uint32_t*)(p.outLo + o) = lp;
                }
            }
        }
    }
}

// ---------------------------------------------------------------------------
// Embedding gather + hi/lo split
// ---------------------------------------------------------------------------
__global__ void embed_split(const int* __restrict__ x, const float* __restrict__ emb,
                            __nv_bfloat16* __restrict__ hhi, __nv_bfloat16* __restrict__ hlo)
{
    const int r = blockIdx.x;
    const int row = x[r];
    const float4 f = ((const float4*)(emb + (size_t)row * EDIM))[threadIdx.x];
    const size_t o = (size_t)r * EDIM + threadIdx.x * 4;
    __nv_bfloat16 h, l;
    split2(f.x, h, l); hhi[o+0] = h; hlo[o+0] = l;
    split2(f.y, h, l); hhi[o+1] = h; hlo[o+1] = l;
    split2(f.z, h, l); hhi[o+2] = h; hlo[o+2] = l;
    split2(f.w, h, l); hhi[o+3] = h; hlo[o+3] = l;
}

// ---------------------------------------------------------------------------
// Transpose + hi/lo split: src fp32 [R,C] -> dst bf16 [C,R] (hi,lo)
// ---------------------------------------------------------------------------
__global__ void transpose_split(const float* __restrict__ src,
                                __nv_bfloat16* __restrict__ dhi,
                                __nv_bfloat16* __restrict__ dlo,
                                int R, int C, size_t szSrc, size_t szDst)
{
    __shared__ float t[32][33];
    src += (size_t)blockIdx.z * szSrc;
    dhi += (size_t)blockIdx.z * szDst;
    dlo += (size_t)blockIdx.z * szDst;
    const int c0 = blockIdx.x * 32, r0 = blockIdx.y * 32;
    const int tx = threadIdx.x, ty = threadIdx.y;
    #pragma unroll
    for (int j = 0; j < 4; j++)
        t[ty + j*8][tx] = src[(size_t)(r0 + ty + j*8) * C + c0 + tx];
    __syncthreads();
    #pragma unroll
    for (int j = 0; j < 4; j++) {
        const float v = t[tx][ty + j*8];
        __nv_bfloat16 h, l;
        split2(v, h, l);
        const size_t o = (size_t)(c0 + ty + j*8) * R + r0 + tx;
        dhi[o] = h; dlo[o] = l;
    }
}

// ---------------------------------------------------------------------------
// V transpose, bf16 hi/lo -> bf16 hi/lo: [SEQ,EDIM] -> [EDIM,SEQ], per batch z
// ---------------------------------------------------------------------------
__global__ void transpose_v(const uint16_t* __restrict__ shi,
                            const uint16_t* __restrict__ slo,
                            uint16_t* __restrict__ dhi, uint16_t* __restrict__ dlo)
{
    __shared__ uint32_t t[32][33];
    const int b = blockIdx.z;
    const int c0 = blockIdx.x * 32;   // e
    const int r0 = blockIdx.y * 32;   // s
    const int tx = threadIdx.x, ty = threadIdx.y;
    const size_t srcBase = (size_t)b * SEQ * EDIM;
    #pragma unroll
    for (int j = 0; j < 4; j++) {
        const size_t idx = srcBase + (size_t)(r0 + ty + j*8) * EDIM + c0 + tx;
        t[ty + j*8][tx] = (uint32_t)shi[idx] | ((uint32_t)slo[idx] << 16);
    }
    __syncthreads();
    const size_t dstBase = (size_t)b * EDIM * SEQ;
    #pragma unroll
    for (int j = 0; j < 4; j++) {
        const uint32_t v = t[tx][ty + j*8];
        const size_t o = dstBase + (size_t)(c0 + ty + j*8) * SEQ + r0 + tx;
        dhi[o] = (uint16_t)(v & 0xFFFF);
        dlo[o] = (uint16_t)(v >> 16);
    }
}

// ---------------------------------------------------------------------------
// Masked softmax (keep t >= s), fp32 in -> bf16 hi/lo out.
// Zero-fill ONLY t in [floor(s/128)*128, s): w@v with triK never reads t < m0.
// ---------------------------------------------------------------------------
__global__ void __launch_bounds__(256) softmax_split(const float* __restrict__ sc,
                                                     __nv_bfloat16* __restrict__ whi,
                                                     __nv_bfloat16* __restrict__ wlo)
{
    const int s = blockIdx.x, b = blockIdx.y;
    const size_t base = ((size_t)b * SEQ + s) * SEQ;
    const float* row = sc + base;
    const int tid = threadIdx.x;
    __shared__ float red[256];

    float m = -1e30f;
    for (int t = s + tid; t < SEQ; t += 256) m = fmaxf(m, row[t]);
    red[tid] = m; __syncthreads();
    #pragma unroll
    for (int o = 128; o > 0; o >>= 1) {
        if (tid < o) red[tid] = fmaxf(red[tid], red[tid + o]);
        __syncthreads();
    }
    m = red[0]; __syncthreads();

    float ev[8];
    float sum = 0.f;
    {
        int j = 0;
        for (int t = s + tid; t < SEQ; t += 256, j++) {
            const float e = expf(row[t] - m);
            ev[j] = e;
            sum += e;
        }
    }
    red[tid] = sum; __syncthreads();
    #pragma unroll
    for (int o = 128; o > 0; o >>= 1) {
        if (tid < o) red[tid] += red[tid + o];
        __syncthreads();
    }
    const float inv = 1.f / red[0];

    // zero only the readable masked region [m0, s)
    const int m0 = s & ~127;
    for (int t = m0 + tid; t < s; t += 256) {
        whi[base + t] = __float2bfloat16(0.f);
        wlo[base + t] = __float2bfloat16(0.f);
    }
    {
        int j = 0;
        for (int t = s + tid; t < SEQ; t += 256, j++) {
            __nv_bfloat16 h, l;
            split2(ev[j] * inv, h, l);
            whi[base + t] = h;
            wlo[base + t] = l;
        }
    }
}

// ---------------------------------------------------------------------------
// Host
// ---------------------------------------------------------------------------
template <typename T>
static T* sym(const void* s) { void* p = nullptr; cudaGetSymbolAddress(&p, s); return (T*)p; }

static void launch_gemm(GP& p, int M, int N, int Z, cudaStream_t st)
{
    dim3 g(N / 256, M / 128, Z);
    tgemm<<<g, 256, GEMM_SMEM, st>>>(p);
}

extern "C" void kernel_launch(void* const* d_in, const int* in_sizes, int n_in,
                              void* d_out, int out_size)
{
    const int*   x   = (const int*)  d_in[0];
    const float* emb = (const float*)d_in[1];
    const float* Wq  = (const float*)d_in[2];
    const float* bq  = (const float*)d_in[3];
    const float* Wk  = (const float*)d_in[4];
    const float* bk  = (const float*)d_in[5];
    const float* Wv  = (const float*)d_in[6];
    const float* bv  = (const float*)d_in[7];
    const float* W1  = (const float*)d_in[8];
    const float* b1  = (const float*)d_in[9];
    const float* W2  = (const float*)d_in[10];
    const float* b2  = (const float*)d_in[11];
    float* out = (float*)d_out;

    static cudaStream_t s2 = nullptr, s3 = nullptr;
    static cudaEvent_t ev0 = nullptr, evW = nullptr, evV = nullptr, evVT = nullptr;
    if (!s2) {
        cudaFuncSetAttribute(tgemm, cudaFuncAttributeMaxDynamicSharedMemorySize, GEMM_SMEM);
        cudaStreamCreateWithFlags(&s2, cudaStreamNonBlocking);
        cudaStreamCreateWithFlags(&s3, cudaStreamNonBlocking);
        cudaEventCreateWithFlags(&ev0, cudaEventDisableTiming);
        cudaEventCreateWithFlags(&evW, cudaEventDisableTiming);
        cudaEventCreateWithFlags(&evV, cudaEventDisableTiming);
        cudaEventCreateWithFlags(&evVT, cudaEventDisableTiming);
    }

    __nv_bfloat16* hhi = sym<__nv_bfloat16>(g_hhi);
    __nv_bfloat16* hlo = sym<__nv_bfloat16>(g_hlo);
    __nv_bfloat16* qhi = sym<__nv_bfloat16>(g_qhi);
    __nv_bfloat16* qlo = sym<__nv_bfloat16>(g_qlo);
    __nv_bfloat16* khi = sym<__nv_bfloat16>(g_khi);
    __nv_bfloat16* klo = sym<__nv_bfloat16>(g_klo);
    __nv_bfloat16* vhl = sym<__nv_bfloat16>(g_vhl);
    __nv_bfloat16* vhi = vhl;
    __nv_bfloat16* vlo = vhl + (size_t)NROWS * EDIM;
    __nv_bfloat16* vthi= sym<__nv_bfloat16>(g_vthi);
    __nv_bfloat16* vtlo= sym<__nv_bfloat16>(g_vtlo);
    float*         sc  = sym<float>(g_sc);
    __nv_bfloat16* whi = sym<__nv_bfloat16>(g_whi);
    __nv_bfloat16* wlo = sym<__nv_bfloat16>(g_wlo);
    __nv_bfloat16* mhi = sym<__nv_bfloat16>(g_mhi);
    __nv_bfloat16* mlo = sym<__nv_bfloat16>(g_mlo);
    __nv_bfloat16* wqt = sym<__nv_bfloat16>(g_wqt);
    __nv_bfloat16* wkt = sym<__nv_bfloat16>(g_wkt);
    __nv_bfloat16* wvt = sym<__nv_bfloat16>(g_wvt);
    __nv_bfloat16* w1t = sym<__nv_bfloat16>(g_w1t);
    __nv_bfloat16* w2t = sym<__nv_bfloat16>(g_w2t);

    const size_t EE = (size_t)EDIM * EDIM;
    const size_t EM = (size_t)EDIM * MDIM;
    const cudaStream_t s0 = 0;

    dim3 tb(32, 8);

    // fork s3: W1/W2 transposes overlap the attention phase
    cudaEventRecord(ev0, s0);
    cudaStreamWaitEvent(s3, ev0, 0);
    transpose_split<<<dim3(MDIM/32, EDIM/32, NLAY), tb, 0, s3>>>(W1, w1t, w1t + (size_t)NLAY*EM, EDIM, MDIM, EM, EM);
    transpose_split<<<dim3(EDIM/32, MDIM/32, NLAY), tb, 0, s3>>>(W2, w2t, w2t + (size_t)NLAY*EM, MDIM, EDIM, EM, EM);
    cudaEventRecord(evW, s3);

    // main stream: QKV weight transposes + embedding
    transpose_split<<<dim3(EDIM/32, EDIM/32, 1), tb, 0, s0>>>(Wq, wqt, wqt + EE, EDIM, EDIM, 0, 0);
    transpose_split<<<dim3(EDIM/32, EDIM/32, 1), tb, 0, s0>>>(Wk, wkt, wkt + EE, EDIM, EDIM, 0, 0);
    transpose_split<<<dim3(EDIM/32, EDIM/32, 1), tb, 0, s0>>>(Wv, wvt, wvt + EE, EDIM, EDIM, 0, 0);
    embed_split<<<NROWS, 256, 0, s0>>>(x, emb, hhi, hlo);

    GP p = {};
    p.Ahi = hhi; p.Alo = hlo; p.ldA = EDIM; p.ldB = EDIM; p.ldC = EDIM;
    p.K = EDIM; p.scale = 1.f; p.relu = 0; p.maskSkip = 0; p.triK = 0;
    p.szA = p.szB = p.szC = 0;

    p.Bhi = wqt; p.Blo = wqt + EE; p.bias = bq;
    p.outHi = qhi; p.outLo = qlo; p.outF = nullptr;
    launch_gemm(p, NROWS, EDIM, 1, s0);

    p.Bhi = wkt; p.Blo = wkt + EE; p.bias = bk;
    p.outHi = khi; p.outLo = klo;
    launch_gemm(p, NROWS, EDIM, 1, s0);

    p.Bhi = wvt; p.Blo = wvt + EE; p.bias = bv;
    p.outHi = vhi; p.outLo = vlo; p.outF = nullptr;
    launch_gemm(p, NROWS, EDIM, 1, s0);
    cudaEventRecord(evV, s0);

    // fork s2: v transpose overlaps the scores GEMM
    cudaStreamWaitEvent(s2, evV, 0);
    transpose_v<<<dim3(EDIM/32, SEQ/32, BATCH), tb, 0, s2>>>((const uint16_t*)vhi, (const uint16_t*)vlo,
                                                             (uint16_t*)vthi, (uint16_t*)vtlo);
    cudaEventRecord(evVT, s2);

    // scores = scale * q k^T  (batched, masked-tile skip)
    p.Ahi = qhi; p.Alo = qlo; p.Bhi = khi; p.Blo = klo;
    p.ldA = EDIM; p.ldB = EDIM; p.ldC = SEQ; p.K = EDIM;
    p.szA = (size_t)SEQ * EDIM; p.szB = (size_t)SEQ * EDIM; p.szC = (size_t)SEQ * SEQ;
    p.bias = nullptr; p.outF = sc; p.outHi = nullptr; p.outLo = nullptr;
    p.scale = 1.f / 32.f; p.relu = 0; p.maskSkip = 1; p.triK = 0;
    launch_gemm(p, SEQ, SEQ, BATCH, s0);

    softmax_split<<<dim3(SEQ, BATCH), 256, 0, s0>>>(sc, whi, wlo);

    // join s2 before w@v
    cudaStreamWaitEvent(s0, evVT, 0);

    // h = relu(w v)  (batched, triangular K skip)
    p.Ahi = whi; p.Alo = wlo; p.Bhi = vthi; p.Blo = vtlo;
    p.ldA = SEQ; p.ldB = SEQ; p.ldC = EDIM; p.K = SEQ;
    p.szA = (size_t)SEQ * SEQ; p.szB = (size_t)EDIM * SEQ; p.szC = (size_t)SEQ * EDIM;
    p.bias = nullptr; p.outF = nullptr; p.outHi = hhi; p.outLo = hlo;
    p.scale = 1.f; p.relu = 1; p.maskSkip = 0; p.triK = 1;
    launch_gemm(p, SEQ, EDIM, BATCH, s0);

    // join s1 before MLP
    cudaStreamWaitEvent(s0, evW, 0);

    // MLP stack
    p.szA = p.szB = p.szC = 0;
    p.maskSkip = 0; p.triK = 0;
    __nv_bfloat16 *curHi = hhi, *curLo = hlo;
    __nv_bfloat16 *altHi = qhi, *altLo = qlo;
    for (int i = 0; i < NLAY; i++) {
        p.Ahi = curHi; p.Alo = curLo;
        p.Bhi = w1t + (size_t)i * EM; p.Blo = w1t + (size_t)(NLAY + i) * EM;
        p.ldA = EDIM; p.ldB = EDIM; p.ldC = MDIM; p.K = EDIM;
        p.bias = b1 + (size_t)i * MDIM;
        p.outHi = mhi; p.outLo = mlo; p.outF = nullptr;
        p.scale = 1.f; p.relu = 1;
        launch_gemm(p, NROWS, MDIM, 1, s0);

        p.Ahi = mhi; p.Alo = mlo;
        p.Bhi = w2t + (size_t)i * EM; p.Blo = w2t + (size_t)(NLAY + i) * EM;
        p.ldA = MDIM; p.ldB = MDIM; p.ldC = EDIM; p.K = MDIM;
        p.bias = b2 + (size_t)i * EDIM;
        if (i == NLAY - 1) {
            p.outHi = nullptr; p.outLo = nullptr; p.outF = out;
        } else {
            p.outHi = altHi; p.outLo = altLo; p.outF = nullptr;
        }
        launch_gemm(p, NROWS, EDIM, 1, s0);

        __nv_bfloat16* t;
        t = curHi; curHi = altHi; altHi = t;
        t = curLo; curLo = altLo; altLo = t;
    }
}

// round 14
// speedup vs baseline: 1.0169x; 1.0002x over previous
#include <cuda_runtime.h>
#include <cuda_bf16.h>
#include <math.h>
#include <stdint.h>

// ---------------------------------------------------------------------------
// Problem constants
// ---------------------------------------------------------------------------
#define VOCAB 32000
#define EDIM  1024
#define MDIM  4096
#define NLAY  4
#define BATCH 4
#define SEQ   2048
#define NROWS (BATCH*SEQ)   // 8192

// ---------------------------------------------------------------------------
// Static device scratch
// ---------------------------------------------------------------------------
__device__ __nv_bfloat16 g_hhi [NROWS * EDIM];
__device__ __nv_bfloat16 g_hlo [NROWS * EDIM];
__device__ __nv_bfloat16 g_qhi [NROWS * EDIM];
__device__ __nv_bfloat16 g_qlo [NROWS * EDIM];
__device__ __nv_bfloat16 g_khi [NROWS * EDIM];
__device__ __nv_bfloat16 g_klo [NROWS * EDIM];
__device__ __nv_bfloat16 g_vhl [(size_t)2 * NROWS * EDIM];   // [hi | lo]
__device__ __nv_bfloat16 g_vthi[(size_t)BATCH * EDIM * SEQ];
__device__ __nv_bfloat16 g_vtlo[(size_t)BATCH * EDIM * SEQ];
__device__ float         g_sc  [(size_t)BATCH * SEQ * SEQ];
__device__ __nv_bfloat16 g_whi [(size_t)BATCH * SEQ * SEQ];
__device__ __nv_bfloat16 g_wlo [(size_t)BATCH * SEQ * SEQ];
__device__ __nv_bfloat16 g_mhi [(size_t)NROWS * MDIM];
__device__ __nv_bfloat16 g_mlo [(size_t)NROWS * MDIM];
__device__ __nv_bfloat16 g_wqt [2 * EDIM * EDIM];
__device__ __nv_bfloat16 g_wkt [2 * EDIM * EDIM];
__device__ __nv_bfloat16 g_wvt [2 * EDIM * EDIM];
__device__ __nv_bfloat16 g_w1t [(size_t)2 * NLAY * MDIM * EDIM];
__device__ __nv_bfloat16 g_w2t [(size_t)2 * NLAY * EDIM * MDIM];

// ---------------------------------------------------------------------------
// PTX helpers (valid at plain compute_103 target)
// ---------------------------------------------------------------------------
#define CP_ASYNC16(dst, src) \
    asm volatile("cp.async.cg.shared.global [%0], [%1], 16;" :: "r"(dst), "l"(src))
#define CP_COMMIT() asm volatile("cp.async.commit_group;" ::: "memory")
#define CP_WAIT(n)  asm volatile("cp.async.wait_group %0;" :: "n"(n) : "memory")

__device__ __forceinline__ uint32_t smem_u32(const void* p) {
    uint32_t a;
    asm("{ .reg .u64 t; cvta.to.shared.u64 t, %1; cvt.u32.u64 %0, t; }"
        : "=r"(a) : "l"(p));
    return a;
}

#define LDSM4(R, A) \
    asm volatile("ldmatrix.sync.aligned.m8n8.x4.shared.b16 {%0,%1,%2,%3}, [%4];" \
        : "=r"((R)[0]), "=r"((R)[1]), "=r"((R)[2]), "=r"((R)[3]) : "r"(A))

__device__ __forceinline__ void mma16816(float* c, const uint32_t* a, const uint32_t* b) {
    asm volatile(
        "mma.sync.aligned.m16n8k16.row.col.f32.bf16.bf16.f32 "
        "{%0,%1,%2,%3}, {%4,%5,%6,%7}, {%8,%9}, {%0,%1,%2,%3};"
        : "+f"(c[0]), "+f"(c[1]), "+f"(c[2]), "+f"(c[3])
        : "r"(a[0]), "r"(a[1]), "r"(a[2]), "r"(a[3]), "r"(b[0]), "r"(b[1]));
}

__device__ __forceinline__ void split2(float v, __nv_bfloat16& hi, __nv_bfloat16& lo) {
    hi = __float2bfloat16(v);
    lo = __float2bfloat16(v - __bfloat162float(hi));
}

// ---------------------------------------------------------------------------
// HMMA GEMM (round-6 champion): out = act(scale*(Ahi+Alo)(Bhi+Blo)^T + bias)
//   A [M,K] K-major, B [N,K] K-major. CTA tile 128x256, 8 warps (64x64 each),
//   BK=64, 2-stage cp.async pipeline, interleaved LDSM, pass-major MMA order.
// ---------------------------------------------------------------------------
struct GP {
    const __nv_bfloat16 *Ahi, *Alo, *Bhi, *Blo;
    const float* bias;
    float* outF;
    __nv_bfloat16 *outHi, *outLo;
    int K, ldA, ldB, ldC;
    size_t szA, szB, szC;
    float scale;
    int relu;
    int maskSkip;
    int triK;
};

#define BK      64
#define APITCH  72
#define TILEA   (128*APITCH*2)
#define TILEBB  (256*APITCH*2)
#define STGB    (2*TILEA + 2*TILEBB)
#define NSTG    2
#define GEMM_SMEM (NSTG*STGB)      // 221184

#define OFF_AHI 0
#define OFF_ALO (TILEA)
#define OFF_BHI (2*TILEA)
#define OFF_BLO (2*TILEA + TILEBB)

__global__ void __launch_bounds__(256, 1) tgemm(GP p)
{
    const int m0 = blockIdx.y * 128;
    const int n0 = blockIdx.x * 256;
    if (p.maskSkip && (n0 + 256 <= m0)) return;

    extern __shared__ char smem[];
    const uint32_t sbase = smem_u32(smem);

    const int tid  = threadIdx.x;
    const int wid  = tid >> 5;
    const int lane = tid & 31;
    const int g    = lane >> 2;
    const int tg   = lane & 3;
    const int wm0 = (wid & 1) * 64;
    const int wn0 = (wid >> 1) * 64;

    const size_t zA = (size_t)blockIdx.z * p.szA;
    const size_t zB = (size_t)blockIdx.z * p.szB;
    const size_t zC = (size_t)blockIdx.z * p.szC;

    const char* aHi = (const char*)(p.Ahi + zA + (size_t)m0 * p.ldA);
    const char* aLo = (const char*)(p.Alo + zA + (size_t)m0 * p.ldA);
    const char* bHi = (const char*)(p.Bhi + zB + (size_t)n0 * p.ldB);
    const char* bLo = (const char*)(p.Blo + zB + (size_t)n0 * p.ldB);
    const size_t rsA = (size_t)p.ldA * 2;
    const size_t rsB = (size_t)p.ldB * 2;

    const int l15 = lane & 15;
    const uint32_t aoff = (uint32_t)(((wm0 + l15) * APITCH + ((lane >> 4) * 8)) * 2);
    const int bN  = ((lane & 16) >> 1) + (lane & 7);
    const uint32_t boff = (uint32_t)(((wn0 + bN) * APITCH + (lane & 8)) * 2);

    const int r0c = tid >> 3;
    const int ccc = (tid & 7) * 16;

    const int NC = p.K / BK;
    const int c0 = p.triK ? (m0 / BK) : 0;
    const int NCr = NC - c0;

    auto load_chunk = [&](int c, int stg) {
        const size_t kb = (size_t)c * BK * 2;
        const uint32_t sb = sbase + stg * STGB;
        #pragma unroll
        for (int h = 0; h < 4; h++) {
            const int row = r0c + h * 32;
            const uint32_t doff = row * (APITCH*2) + ccc;
            const size_t goA = (size_t)row * rsA + kb + ccc;
            CP_ASYNC16(sb + OFF_AHI + doff, aHi + goA);
            CP_ASYNC16(sb + OFF_ALO + doff, aLo + goA);
        }
        #pragma unroll
        for (int h = 0; h < 8; h++) {
            const int row = r0c + h * 32;
            const uint32_t doff = row * (APITCH*2) + ccc;
            const size_t goB = (size_t)row * rsB + kb + ccc;
            CP_ASYNC16(sb + OFF_BHI + doff, bHi + goB);
            CP_ASYNC16(sb + OFF_BLO + doff, bLo + goB);
        }
        CP_COMMIT();
    };

    float acc[4][8][4];
    #pragma unroll
    for (int a = 0; a < 4; a++)
        #pragma unroll
        for (int b = 0; b < 8; b++)
            #pragma unroll
            for (int q = 0; q < 4; q++) acc[a][b][q] = 0.f;

    load_chunk(c0 + 0, 0);
    load_chunk(c0 + 1, 1);

    for (int cr = 0; cr < NCr; cr++) {
        const int stg = cr & 1;
        if (cr + 1 < NCr) CP_WAIT(1);
        else              CP_WAIT(0);
        __syncthreads();

        const uint32_t sb = sbase + stg * STGB;
        #pragma unroll
        for (int kk = 0; kk < BK; kk += 16) {
            uint32_t ah[4][4], al[4][4];
            #pragma unroll
            for (int mt = 0; mt < 4; mt++) {
                const uint32_t ao = sb + aoff + mt*(16*APITCH*2) + kk*2;
                LDSM4(ah[mt], ao);
                LDSM4(al[mt], ao + TILEA);
            }
            #pragma unroll
            for (int ntp = 0; ntp < 4; ntp++) {
                uint32_t bh[4], bl[4];
                const uint32_t bo = sb + OFF_BHI + boff + ntp*(16*APITCH*2) + kk*2;
                LDSM4(bh, bo);
                LDSM4(bl, bo + TILEBB);
                #pragma unroll
                for (int mt = 0; mt < 4; mt++)
                    #pragma unroll
                    for (int nt = 0; nt < 2; nt++)
                        mma16816(acc[mt][ntp*2+nt], ah[mt], &bh[nt*2]);
                #pragma unroll
                for (int mt = 0; mt < 4; mt++)
                    #pragma unroll
                    for (int nt = 0; nt < 2; nt++)
                        mma16816(acc[mt][ntp*2+nt], ah[mt], &bl[nt*2]);
                #pragma unroll
                for (int mt = 0; mt < 4; mt++)
                    #pragma unroll
                    for (int nt = 0; nt < 2; nt++)
                        mma16816(acc[mt][ntp*2+nt], al[mt], &bh[nt*2]);
            }
        }

        __syncthreads();
        if (cr + NSTG < NCr) load_chunk(c0 + cr + NSTG, stg);
    }

    float2 bb[8];
    #pragma unroll
    for (int nt = 0; nt < 8; nt++) {
        if (p.bias) bb[nt] = *(const float2*)(p.bias + n0 + wn0 + nt*8 + tg*2);
        else        bb[nt] = make_float2(0.f, 0.f);
    }
    #pragma unroll
    for (int mt = 0; mt < 4; mt++) {
        #pragma unroll
        for (int half = 0; half < 2; half++) {
            const int r = m0 + wm0 + mt*16 + g + half*8;
            #pragma unroll
            for (int nt = 0; nt < 8; nt++) {
                float x0 = acc[mt][nt][half*2+0] * p.scale + bb[nt].x;
                float x1 = acc[mt][nt][half*2+1] * p.scale + bb[nt].y;
                if (p.relu) { x0 = fmaxf(x0, 0.f); x1 = fmaxf(x1, 0.f); }
                const int cc = n0 + wn0 + nt*8 + tg*2;
                const size_t o = zC + (size_t)r * p.ldC + cc;
                if (p.outF)
                    *(float2*)(p.outF + o) = make_float2(x0, x1);
                if (p.outHi) {
                    __nv_bfloat16 h0, l0, h1, l1;
                    split2(x0, h0, l0);
                    split2(x1, h1, l1);
                    uint32_t hp = (uint32_t)__bfloat16_as_ushort(h0) |
                                  ((uint32_t)__bfloat16_as_ushort(h1) << 16);
                    uint32_t lp = (uint32_t)__bfloat16_as_ushort(l0) |
                                  ((uint32_t)__bfloat16_as_ushort(l1) << 16);
                    *(uint32_t*)(p.outHi + o) = hp;
                    *(uint32_t*)(p.outLo + o) = lp;
                }
            }
        }
    }
}

// ---------------------------------------------------------------------------
// Embedding gather + hi/lo split
// ---------------------------------------------------------------------------
__global__ void embed_split(const int* __restrict__ x, const float* __restrict__ emb,
                            __nv_bfloat16* __restrict__ hhi, __nv_bfloat16* __restrict__ hlo)
{
    const int r = blockIdx.x;
    const int row = x[r];
    const float4 f = ((const float4*)(emb + (size_t)row * EDIM))[threadIdx.x];
    const size_t o = (size_t)r * EDIM + threadIdx.x * 4;
    __nv_bfloat16 h, l;
    split2(f.x, h, l); hhi[o+0] = h; hlo[o+0] = l;
    split2(f.y, h, l); hhi[o+1] = h; hlo[o+1] = l;
    split2(f.z, h, l); hhi[o+2] = h; hlo[o+2] = l;
    split2(f.w, h, l); hhi[o+3] = h; hlo[o+3] = l;
}

// ---------------------------------------------------------------------------
// Transpose + hi/lo split: src fp32 [R,C] -> dst bf16 [C,R] (hi,lo)
// ---------------------------------------------------------------------------
__global__ void transpose_split(const float* __restrict__ src,
                                __nv_bfloat16* __restrict__ dhi,
                                __nv_bfloat16* __restrict__ dlo,
                                int R, int C, size_t szSrc, size_t szDst)
{
    __shared__ float t[32][33];
    src += (size_t)blockIdx.z * szSrc;
    dhi += (size_t)blockIdx.z * szDst;
    dlo += (size_t)blockIdx.z * szDst;
    const int c0 = blockIdx.x * 32, r0 = blockIdx.y * 32;
    const int tx = threadIdx.x, ty = threadIdx.y;
    #pragma unroll
    for (int j = 0; j < 4; j++)
        t[ty + j*8][tx] = src[(size_t)(r0 + ty + j*8) * C + c0 + tx];
    __syncthreads();
    #pragma unroll
    for (int j = 0; j < 4; j++) {
        const float v = t[tx][ty + j*8];
        __nv_bfloat16 h, l;
        split2(v, h, l);
        const size_t o = (size_t)(c0 + ty + j*8) * R + r0 + tx;
        dhi[o] = h; dlo[o] = l;
    }
}

// ---------------------------------------------------------------------------
// V transpose, bf16 hi/lo -> bf16 hi/lo: [SEQ,EDIM] -> [EDIM,SEQ], per batch z
// ---------------------------------------------------------------------------
__global__ void transpose_v(const uint16_t* __restrict__ shi,
                            const uint16_t* __restrict__ slo,
                            uint16_t* __restrict__ dhi, uint16_t* __restrict__ dlo)
{
    __shared__ uint32_t t[32][33];
    const int b = blockIdx.z;
    const int c0 = blockIdx.x * 32;   // e
    const int r0 = blockIdx.y * 32;   // s
    const int tx = threadIdx.x, ty = threadIdx.y;
    const size_t srcBase = (size_t)b * SEQ * EDIM;
    #pragma unroll
    for (int j = 0; j < 4; j++) {
        const size_t idx = srcBase + (size_t)(r0 + ty + j*8) * EDIM + c0 + tx;
        t[ty + j*8][tx] = (uint32_t)shi[idx] | ((uint32_t)slo[idx] << 16);
    }
    __syncthreads();
    const size_t dstBase = (size_t)b * EDIM * SEQ;
    #pragma unroll
    for (int j = 0; j < 4; j++) {
        const uint32_t v = t[tx][ty + j*8];
        const size_t o = dstBase + (size_t)(c0 + ty + j*8) * SEQ + r0 + tx;
        dhi[o] = (uint16_t)(v & 0xFFFF);
        dlo[o] = (uint16_t)(v >> 16);
    }
}

// ---------------------------------------------------------------------------
// Fast masked softmax (keep t >= s): register-cached row, __expf, warp-shuffle
// reductions. Zero-fill only [floor(s/128)*128, s) (triK never reads below).
// ---------------------------------------------------------------------------
__global__ void __launch_bounds__(256) softmax_split(const float* __restrict__ sc,
                                                     __nv_bfloat16* __restrict__ whi,
                                                     __nv_bfloat16* __restrict__ wlo)
{
    const int s = blockIdx.x, b = blockIdx.y;
    const size_t base = ((size_t)b * SEQ + s) * SEQ;
    const float* row = sc + base;
    const int tid = threadIdx.x;
    __shared__ float redm[8], reds[8];

    float rv[8];
    float m = -1e30f;
    {
        int j = 0;
        for (int t = s + tid; t < SEQ; t += 256, j++) {
            rv[j] = row[t];
            m = fmaxf(m, rv[j]);
        }
    }
    #pragma unroll
    for (int o = 16; o > 0; o >>= 1) m = fmaxf(m, __shfl_xor_sync(0xFFFFFFFFu, m, o));
    if ((tid & 31) == 0) redm[tid >> 5] = m;
    __syncthreads();
    m = redm[0];
    #pragma unroll
    for (int w = 1; w < 8; w++) m = fmaxf(m, redm[w]);

    float sum = 0.f;
    {
        int j = 0;
        for (int t = s + tid; t < SEQ; t += 256, j++) {
            rv[j] = __expf(rv[j] - m);
            sum += rv[j];
        }
    }
    #pragma unroll
    for (int o = 16; o > 0; o >>= 1) sum += __shfl_xor_sync(0xFFFFFFFFu, sum, o);
    if ((tid & 31) == 0) reds[tid >> 5] = sum;
    __syncthreads();
    sum = reds[0];
    #pragma unroll
    for (int w = 1; w < 8; w++) sum += reds[w];
    const float inv = 1.f / sum;

    const int m0 = s & ~127;
    for (int t = m0 + tid; t < s; t += 256) {
        whi[base + t] = __float2bfloat16(0.f);
        wlo[base + t] = __float2bfloat16(0.f);
    }
    {
        int j = 0;
        for (int t = s + tid; t < SEQ; t += 256, j++) {
            __nv_bfloat16 h, l;
            split2(rv[j] * inv, h, l);
            whi[base + t] = h;
            wlo[base + t] = l;
        }
    }
}

// ---------------------------------------------------------------------------
// Host
// ---------------------------------------------------------------------------
template <typename T>
static T* sym(const void* s) { void* p = nullptr; cudaGetSymbolAddress(&p, s); return (T*)p; }

static void launch_gemm(GP& p, int M, int N, int Z, cudaStream_t st)
{
    dim3 g(N / 256, M / 128, Z);
    tgemm<<<g, 256, GEMM_SMEM, st>>>(p);
}

extern "C" void kernel_launch(void* const* d_in, const int* in_sizes, int n_in,
                              void* d_out, int out_size)
{
    const int*   x   = (const int*)  d_in[0];
    const float* emb = (const float*)d_in[1];
    const float* Wq  = (const float*)d_in[2];
    const float* bq  = (const float*)d_in[3];
    const float* Wk  = (const float*)d_in[4];
    const float* bk  = (const float*)d_in[5];
    const float* Wv  = (const float*)d_in[6];
    const float* bv  = (const float*)d_in[7];
    const float* W1  = (const float*)d_in[8];
    const float* b1  = (const float*)d_in[9];
    const float* W2  = (const float*)d_in[10];
    const float* b2  = (const float*)d_in[11];
    float* out = (float*)d_out;

    static cudaStream_t s2 = nullptr, s3 = nullptr;
    static cudaEvent_t ev0 = nullptr, evW = nullptr, evQW = nullptr, evV = nullptr, evVT = nullptr;
    if (!s2) {
        cudaFuncSetAttribute(tgemm, cudaFuncAttributeMaxDynamicSharedMemorySize, GEMM_SMEM);
        cudaStreamCreateWithFlags(&s2, cudaStreamNonBlocking);
        cudaStreamCreateWithFlags(&s3, cudaStreamNonBlocking);
        cudaEventCreateWithFlags(&ev0, cudaEventDisableTiming);
        cudaEventCreateWithFlags(&evW, cudaEventDisableTiming);
        cudaEventCreateWithFlags(&evQW, cudaEventDisableTiming);
        cudaEventCreateWithFlags(&evV, cudaEventDisableTiming);
        cudaEventCreateWithFlags(&evVT, cudaEventDisableTiming);
    }

    __nv_bfloat16* hhi = sym<__nv_bfloat16>(g_hhi);
    __nv_bfloat16* hlo = sym<__nv_bfloat16>(g_hlo);
    __nv_bfloat16* qhi = sym<__nv_bfloat16>(g_qhi);
    __nv_bfloat16* qlo = sym<__nv_bfloat16>(g_qlo);
    __nv_bfloat16* khi = sym<__nv_bfloat16>(g_khi);
    __nv_bfloat16* klo = sym<__nv_bfloat16>(g_klo);
    __nv_bfloat16* vhl = sym<__nv_bfloat16>(g_vhl);
    __nv_bfloat16* vhi = vhl;
    __nv_bfloat16* vlo = vhl + (size_t)NROWS * EDIM;
    __nv_bfloat16* vthi= sym<__nv_bfloat16>(g_vthi);
    __nv_bfloat16* vtlo= sym<__nv_bfloat16>(g_vtlo);
    float*         sc  = sym<float>(g_sc);
    __nv_bfloat16* whi = sym<__nv_bfloat16>(g_whi);
    __nv_bfloat16* wlo = sym<__nv_bfloat16>(g_wlo);
    __nv_bfloat16* mhi = sym<__nv_bfloat16>(g_mhi);
    __nv_bfloat16* mlo = sym<__nv_bfloat16>(g_mlo);
    __nv_bfloat16* wqt = sym<__nv_bfloat16>(g_wqt);
    __nv_bfloat16* wkt = sym<__nv_bfloat16>(g_wkt);
    __nv_bfloat16* wvt = sym<__nv_bfloat16>(g_wvt);
    __nv_bfloat16* w1t = sym<__nv_bfloat16>(g_w1t);
    __nv_bfloat16* w2t = sym<__nv_bfloat16>(g_w2t);

    const size_t EE = (size_t)EDIM * EDIM;
    const size_t EM = (size_t)EDIM * MDIM;
    const cudaStream_t s0 = 0;

    dim3 tb(32, 8);

    // fork s3: W1/W2 transposes overlap the attention phase
    cudaEventRecord(ev0, s0);
    cudaStreamWaitEvent(s3, ev0, 0);
    transpose_split<<<dim3(MDIM/32, EDIM/32, NLAY), tb, 0, s3>>>(W1, w1t, w1t + (size_t)NLAY*EM, EDIM, MDIM, EM, EM);
    transpose_split<<<dim3(EDIM/32, MDIM/32, NLAY), tb, 0, s3>>>(W2, w2t, w2t + (size_t)NLAY*EM, MDIM, EDIM, EM, EM);
    cudaEventRecord(evW, s3);

    // fork s2: QKV weight transposes overlap embedding on s0
    cudaStreamWaitEvent(s2, ev0, 0);
    transpose_split<<<dim3(EDIM/32, EDIM/32, 1), tb, 0, s2>>>(Wq, wqt, wqt + EE, EDIM, EDIM, 0, 0);
    transpose_split<<<dim3(EDIM/32, EDIM/32, 1), tb, 0, s2>>>(Wk, wkt, wkt + EE, EDIM, EDIM, 0, 0);
    transpose_split<<<dim3(EDIM/32, EDIM/32, 1), tb, 0, s2>>>(Wv, wvt, wvt + EE, EDIM, EDIM, 0, 0);
    cudaEventRecord(evQW, s2);

    // main stream: embedding
    embed_split<<<NROWS, 256, 0, s0>>>(x, emb, hhi, hlo);
    cudaStreamWaitEvent(s0, evQW, 0);

    GP p = {};
    p.Ahi = hhi; p.Alo = hlo; p.ldA = EDIM; p.ldB = EDIM; p.ldC = EDIM;
    p.K = EDIM; p.scale = 1.f; p.relu = 0; p.maskSkip = 0; p.triK = 0;
    p.szA = p.szB = p.szC = 0;

    p.Bhi = wqt; p.Blo = wqt + EE; p.bias = bq;
    p.outHi = qhi; p.outLo = qlo; p.outF = nullptr;
    launch_gemm(p, NROWS, EDIM, 1, s0);

    p.Bhi = wkt; p.Blo = wkt + EE; p.bias = bk;
    p.outHi = khi; p.outLo = klo;
    launch_gemm(p, NROWS, EDIM, 1, s0);

    p.Bhi = wvt; p.Blo = wvt + EE; p.bias = bv;
    p.outHi = vhi; p.outLo = vlo; p.outF = nullptr;
    launch_gemm(p, NROWS, EDIM, 1, s0);
    cudaEventRecord(evV, s0);

    // fork s2: v transpose overlaps the scores GEMM
    cudaStreamWaitEvent(s2, evV, 0);
    transpose_v<<<dim3(EDIM/32, SEQ/32, BATCH), tb, 0, s2>>>((const uint16_t*)vhi, (const uint16_t*)vlo,
                                                             (uint16_t*)vthi, (uint16_t*)vtlo);
    cudaEventRecord(evVT, s2);

    // scores = scale * q k^T  (batched, masked-tile skip)
    p.Ahi = qhi; p.Alo = qlo; p.Bhi = khi; p.Blo = klo;
    p.ldA = EDIM; p.ldB = EDIM; p.ldC = SEQ; p.K = EDIM;
    p.szA = (size_t)SEQ * EDIM; p.szB = (size_t)SEQ * EDIM; p.szC = (size_t)SEQ * SEQ;
    p.bias = nullptr; p.outF = sc; p.outHi = nullptr; p.outLo = nullptr;
    p.scale = 1.f / 32.f; p.relu = 0; p.maskSkip = 1; p.triK = 0;
    launch_gemm(p, SEQ, SEQ, BATCH, s0);

    softmax_split<<<dim3(SEQ, BATCH), 256, 0, s0>>>(sc, whi, wlo);

    // join s2 before w@v
    cudaStreamWaitEvent(s0, evVT, 0);

    // h = relu(w v)  (batched, triangular K skip)
    p.Ahi = whi; p.Alo = wlo; p.Bhi = vthi; p.Blo = vtlo;
    p.ldA = SEQ; p.ldB = SEQ; p.ldC = EDIM; p.K = SEQ;
    p.szA = (size_t)SEQ * SEQ; p.szB = (size_t)EDIM * SEQ; p.szC = (size_t)SEQ * EDIM;
    p.bias = nullptr; p.outF = nullptr; p.outHi = hhi; p.outLo = hlo;
    p.scale = 1.f; p.relu = 1; p.maskSkip = 0; p.triK = 1;
    launch_gemm(p, SEQ, EDIM, BATCH, s0);

    // join s3 before MLP
    cudaStreamWaitEvent(s0, evW, 0);

    // MLP stack
    p.szA = p.szB = p.szC = 0;
    p.maskSkip = 0; p.triK = 0;
    __nv_bfloat16 *curHi = hhi, *curLo = hlo;
    __nv_bfloat16 *altHi = qhi, *altLo = qlo;
    for (int i = 0; i < NLAY; i++) {
        p.Ahi = curHi; p.Alo = curLo;
        p.Bhi = w1t + (size_t)i * EM; p.Blo = w1t + (size_t)(NLAY + i) * EM;
        p.ldA = EDIM; p.ldB = EDIM; p.ldC = MDIM; p.K = EDIM;
        p.bias = b1 + (size_t)i * MDIM;
        p.outHi = mhi; p.outLo = mlo; p.outF = nullptr;
        p.scale = 1.f; p.relu = 1;
        launch_gemm(p, NROWS, MDIM, 1, s0);

        p.Ahi = mhi; p.Alo = mlo;
        p.Bhi = w2t + (size_t)i * EM; p.Blo = w2t + (size_t)(NLAY + i) * EM;
        p.ldA = MDIM; p.ldB = MDIM; p.ldC = EDIM; p.K = MDIM;
        p.bias = b2 + (size_t)i * EDIM;
        if (i == NLAY - 1) {
            p.outHi = nullptr; p.outLo = nullptr; p.outF = out;
        } else {
            p.outHi = altHi; p.outLo = altLo; p.outF = nullptr;
        }
        launch_gemm(p, NROWS, EDIM, 1, s0);

        __nv_bfloat16* t;
        t = curHi; curHi = altHi; altHi = t;
        t = curLo; curLo = altLo; altLo = t;
    }
}

// round 15
// speedup vs baseline: 1.0173x; 1.0004x over previous
#include <cuda_runtime.h>
#include <cuda_bf16.h>
#include <math.h>
#include <stdint.h>

// ---------------------------------------------------------------------------
// Problem constants
// ---------------------------------------------------------------------------
#define VOCAB 32000
#define EDIM  1024
#define MDIM  4096
#define NLAY  4
#define BATCH 4
#define SEQ   2048
#define NROWS (BATCH*SEQ)   // 8192

// ---------------------------------------------------------------------------
// Static device scratch
// ---------------------------------------------------------------------------
__device__ __nv_bfloat16 g_hhi [NROWS * EDIM];
__device__ __nv_bfloat16 g_hlo [NROWS * EDIM];
__device__ __nv_bfloat16 g_qhi [NROWS * EDIM];
__device__ __nv_bfloat16 g_qlo [NROWS * EDIM];
__device__ __nv_bfloat16 g_khi [NROWS * EDIM];
__device__ __nv_bfloat16 g_klo [NROWS * EDIM];
__device__ float         g_v   [NROWS * EDIM];
__device__ __nv_bfloat16 g_vthi[(size_t)BATCH * EDIM * SEQ];
__device__ __nv_bfloat16 g_vtlo[(size_t)BATCH * EDIM * SEQ];
__device__ float         g_sc  [(size_t)BATCH * SEQ * SEQ];
__device__ __nv_bfloat16 g_whi [(size_t)BATCH * SEQ * SEQ];
__device__ __nv_bfloat16 g_wlo [(size_t)BATCH * SEQ * SEQ];
__device__ __nv_bfloat16 g_mhi [(size_t)NROWS * MDIM];
__device__ __nv_bfloat16 g_mlo [(size_t)NROWS * MDIM];
__device__ __nv_bfloat16 g_wqt [2 * EDIM * EDIM];
__device__ __nv_bfloat16 g_wkt [2 * EDIM * EDIM];
__device__ __nv_bfloat16 g_wvt [2 * EDIM * EDIM];
__device__ __nv_bfloat16 g_w1t [(size_t)2 * NLAY * MDIM * EDIM];
__device__ __nv_bfloat16 g_w2t [(size_t)2 * NLAY * EDIM * MDIM];

// ---------------------------------------------------------------------------
// PTX helpers (valid at plain compute_103 target)
// ---------------------------------------------------------------------------
#define CP_ASYNC16(dst, src) \
    asm volatile("cp.async.cg.shared.global [%0], [%1], 16;" :: "r"(dst), "l"(src))
#define CP_COMMIT() asm volatile("cp.async.commit_group;" ::: "memory")
#define CP_WAIT(n)  asm volatile("cp.async.wait_group %0;" :: "n"(n) : "memory")

__device__ __forceinline__ uint32_t smem_u32(const void* p) {
    uint32_t a;
    asm("{ .reg .u64 t; cvta.to.shared.u64 t, %1; cvt.u32.u64 %0, t; }"
        : "=r"(a) : "l"(p));
    return a;
}

#define LDSM4(R, A) \
    asm volatile("ldmatrix.sync.aligned.m8n8.x4.shared.b16 {%0,%1,%2,%3}, [%4];" \
        : "=r"((R)[0]), "=r"((R)[1]), "=r"((R)[2]), "=r"((R)[3]) : "r"(A))

__device__ __forceinline__ void mma16816(float* c, const uint32_t* a, const uint32_t* b) {
    asm volatile(
        "mma.sync.aligned.m16n8k16.row.col.f32.bf16.bf16.f32 "
        "{%0,%1,%2,%3}, {%4,%5,%6,%7}, {%8,%9}, {%0,%1,%2,%3};"
        : "+f"(c[0]), "+f"(c[1]), "+f"(c[2]), "+f"(c[3])
        : "r"(a[0]), "r"(a[1]), "r"(a[2]), "r"(a[3]), "r"(b[0]), "r"(b[1]));
}

__device__ __forceinline__ void split2(float v, __nv_bfloat16& hi, __nv_bfloat16& lo) {
    hi = __float2bfloat16(v);
    lo = __float2bfloat16(v - __bfloat162float(hi));
}

// ---------------------------------------------------------------------------
// HMMA GEMM: out = act(scale*(Ahi+Alo)(Bhi+Blo)^T + bias)
//   A [M,K] K-major, B [N,K] K-major. CTA tile 128x256, 8 warps (64x64 each),
//   BK=64, 2-stage cp.async pipeline, interleaved LDSM, pass-major MMA order.
// ---------------------------------------------------------------------------
struct GP {
    const __nv_bfloat16 *Ahi, *Alo, *Bhi, *Blo;
    const float* bias;
    float* outF;
    __nv_bfloat16 *outHi, *outLo;
    int K, ldA, ldB, ldC;
    size_t szA, szB, szC;
    float scale;
    int relu;
    int maskSkip;
    int triK;
};

#define BK      64
#define APITCH  72
#define TILEA   (128*APITCH*2)
#define TILEBB  (256*APITCH*2)
#define STGB    (2*TILEA + 2*TILEBB)
#define NSTG    2
#define GEMM_SMEM (NSTG*STGB)      // 221184

#define OFF_AHI 0
#define OFF_ALO (TILEA)
#define OFF_BHI (2*TILEA)
#define OFF_BLO (2*TILEA + TILEBB)

__global__ void __launch_bounds__(256, 1) tgemm(GP p)
{
    const int m0 = blockIdx.y * 128;
    const int n0 = blockIdx.x * 256;
    if (p.maskSkip && (n0 + 256 <= m0)) return;

    extern __shared__ char smem[];
    const uint32_t sbase = smem_u32(smem);

    const int tid  = threadIdx.x;
    const int wid  = tid >> 5;
    const int lane = tid & 31;
    const int g    = lane >> 2;
    const int tg   = lane & 3;
    const int wm0 = (wid & 1) * 64;
    const int wn0 = (wid >> 1) * 64;

    const size_t zA = (size_t)blockIdx.z * p.szA;
    const size_t zB = (size_t)blockIdx.z * p.szB;
    const size_t zC = (size_t)blockIdx.z * p.szC;

    const char* aHi = (const char*)(p.Ahi + zA + (size_t)m0 * p.ldA);
    const char* aLo = (const char*)(p.Alo + zA + (size_t)m0 * p.ldA);
    const char* bHi = (const char*)(p.Bhi + zB + (size_t)n0 * p.ldB);
    const char* bLo = (const char*)(p.Blo + zB + (size_t)n0 * p.ldB);
    const size_t rsA = (size_t)p.ldA * 2;
    const size_t rsB = (size_t)p.ldB * 2;

    const int l15 = lane & 15;
    const uint32_t aoff = (uint32_t)(((wm0 + l15) * APITCH + ((lane >> 4) * 8)) * 2);
    const int bN  = ((lane & 16) >> 1) + (lane & 7);
    const uint32_t boff = (uint32_t)(((wn0 + bN) * APITCH + (lane & 8)) * 2);

    const int r0c = tid >> 3;
    const int ccc = (tid & 7) * 16;

    const int NC = p.K / BK;
    const int c0 = p.triK ? (m0 / BK) : 0;
    const int NCr = NC - c0;

    auto load_chunk = [&](int c, int stg) {
        const size_t kb = (size_t)c * BK * 2;
        const uint32_t sb = sbase + stg * STGB;
        #pragma unroll
        for (int h = 0; h < 4; h++) {
            const int row = r0c + h * 32;
            const uint32_t doff = row * (APITCH*2) + ccc;
            const size_t goA = (size_t)row * rsA + kb + ccc;
            CP_ASYNC16(sb + OFF_AHI + doff, aHi + goA);
            CP_ASYNC16(sb + OFF_ALO + doff, aLo + goA);
        }
        #pragma unroll
        for (int h = 0; h < 8; h++) {
            const int row = r0c + h * 32;
            const uint32_t doff = row * (APITCH*2) + ccc;
            const size_t goB = (size_t)row * rsB + kb + ccc;
            CP_ASYNC16(sb + OFF_BHI + doff, bHi + goB);
            CP_ASYNC16(sb + OFF_BLO + doff, bLo + goB);
        }
        CP_COMMIT();
    };

    float acc[4][8][4];
    #pragma unroll
    for (int a = 0; a < 4; a++)
        #pragma unroll
        for (int b = 0; b < 8; b++)
            #pragma unroll
            for (int q = 0; q < 4; q++) acc[a][b][q] = 0.f;

    load_chunk(c0 + 0, 0);
    load_chunk(c0 + 1, 1);

    for (int cr = 0; cr < NCr; cr++) {
        const int stg = cr & 1;
        if (cr + 1 < NCr) CP_WAIT(1);
        else              CP_WAIT(0);
        __syncthreads();

        const uint32_t sb = sbase + stg * STGB;
        #pragma unroll
        for (int kk = 0; kk < BK; kk += 16) {
            uint32_t ah[4][4], al[4][4];
            #pragma unroll
            for (int mt = 0; mt < 4; mt++) {
                const uint32_t ao = sb + aoff + mt*(16*APITCH*2) + kk*2;
                LDSM4(ah[mt], ao);
                LDSM4(al[mt], ao + TILEA);
            }
            #pragma unroll
            for (int ntp = 0; ntp < 4; ntp++) {
                uint32_t bh[4], bl[4];
                const uint32_t bo = sb + OFF_BHI + boff + ntp*(16*APITCH*2) + kk*2;
                LDSM4(bh, bo);
                LDSM4(bl, bo + TILEBB);
                #pragma unroll
                for (int mt = 0; mt < 4; mt++)
                    #pragma unroll
                    for (int nt = 0; nt < 2; nt++)
                        mma16816(acc[mt][ntp*2+nt], ah[mt], &bh[nt*2]);
                #pragma unroll
                for (int mt = 0; mt < 4; mt++)
                    #pragma unroll
                    for (int nt = 0; nt < 2; nt++)
                        mma16816(acc[mt][ntp*2+nt], ah[mt], &bl[nt*2]);
                #pragma unroll
                for (int mt = 0; mt < 4; mt++)
                    #pragma unroll
                    for (int nt = 0; nt < 2; nt++)
                        mma16816(acc[mt][ntp*2+nt], al[mt], &bh[nt*2]);
            }
        }

        __syncthreads();
        if (cr + NSTG < NCr) load_chunk(c0 + cr + NSTG, stg);
    }

    float2 bb[8];
    #pragma unroll
    for (int nt = 0; nt < 8; nt++) {
        if (p.bias) bb[nt] = *(const float2*)(p.bias + n0 + wn0 + nt*8 + tg*2);
        else        bb[nt] = make_float2(0.f, 0.f);
    }
    #pragma unroll
    for (int mt = 0; mt < 4; mt++) {
        #pragma unroll
        for (int half = 0; half < 2; half++) {
            const int r = m0 + wm0 + mt*16 + g + half*8;
            #pragma unroll
            for (int nt = 0; nt < 8; nt++) {
                float x0 = acc[mt][nt][half*2+0] * p.scale + bb[nt].x;
                float x1 = acc[mt][nt][half*2+1] * p.scale + bb[nt].y;
                if (p.relu) { x0 = fmaxf(x0, 0.f); x1 = fmaxf(x1, 0.f); }
                const int cc = n0 + wn0 + nt*8 + tg*2;
                const size_t o = zC + (size_t)r * p.ldC + cc;
                if (p.outF)
                    *(float2*)(p.outF + o) = make_float2(x0, x1);
                if (p.outHi) {
                    __nv_bfloat16 h0, l0, h1, l1;
                    split2(x0, h0, l0);
                    split2(x1, h1, l1);
                    uint32_t hp = (uint32_t)__bfloat16_as_ushort(h0) |
                                  ((uint32_t)__bfloat16_as_ushort(h1) << 16);
                    uint32_t lp = (uint32_t)__bfloat16_as_ushort(l0) |
                                  ((uint32_t)__bfloat16_as_ushort(l1) << 16);
                    *(uint32_t*)(p.outHi + o) = hp;
                    *(uint32_t*)(p.outLo + o) = lp;
                }
            }
        }
    }
}

// ---------------------------------------------------------------------------
// Embedding gather + hi/lo split
// ---------------------------------------------------------------------------
__global__ void embed_split(const int* __restrict__ x, const float* __restrict__ emb,
                            __nv_bfloat16* __restrict__ hhi, __nv_bfloat16* __restrict__ hlo)
{
    const int r = blockIdx.x;
    const int row = x[r];
    const float4 f = ((const float4*)(emb + (size_t)row * EDIM))[threadIdx.x];
    const size_t o = (size_t)r * EDIM + threadIdx.x * 4;
    __nv_bfloat16 h, l;
    split2(f.x, h, l); hhi[o+0] = h; hlo[o+0] = l;
    split2(f.y, h, l); hhi[o+1] = h; hlo[o+1] = l;
    split2(f.z, h, l); hhi[o+2] = h; hlo[o+2] = l;
    split2(f.w, h, l); hhi[o+3] = h; hlo[o+3] = l;
}

// ---------------------------------------------------------------------------
// Transpose + hi/lo split: src fp32 [R,C] -> dst bf16 [C,R] (hi,lo)
// ---------------------------------------------------------------------------
__global__ void transpose_split(const float* __restrict__ src,
                                __nv_bfloat16* __restrict__ dhi,
                                __nv_bfloat16* __restrict__ dlo,
                                int R, int C, size_t szSrc, size_t szDst)
{
    __shared__ float t[32][33];
    src += (size_t)blockIdx.z * szSrc;
    dhi += (size_t)blockIdx.z * szDst;
    dlo += (size_t)blockIdx.z * szDst;
    const int c0 = blockIdx.x * 32, r0 = blockIdx.y * 32;
    const int tx = threadIdx.x, ty = threadIdx.y;
    #pragma unroll
    for (int j = 0; j < 4; j++)
        t[ty + j*8][tx] = src[(size_t)(r0 + ty + j*8) * C + c0 + tx];
    __syncthreads();
    #pragma unroll
    for (int j = 0; j < 4; j++) {
        const float v = t[tx][ty + j*8];
        __nv_bfloat16 h, l;
        split2(v, h, l);
        const size_t o = (size_t)(c0 + ty + j*8) * R + r0 + tx;
        dhi[o] = h; dlo[o] = l;
    }
}

// ---------------------------------------------------------------------------
// Masked softmax (keep t >= s), fp32 in -> bf16 hi/lo out, exp cached in regs
// ---------------------------------------------------------------------------
__global__ void __launch_bounds__(256) softmax_split(const float* __restrict__ sc,
                                                     __nv_bfloat16* __restrict__ whi,
                                                     __nv_bfloat16* __restrict__ wlo)
{
    const int s = blockIdx.x, b = blockIdx.y;
    const size_t base = ((size_t)b * SEQ + s) * SEQ;
    const float* row = sc + base;
    const int tid = threadIdx.x;
    __shared__ float red[256];

    float m = -1e30f;
    for (int t = s + tid; t < SEQ; t += 256) m = fmaxf(m, row[t]);
    red[tid] = m; __syncthreads();
    #pragma unroll
    for (int o = 128; o > 0; o >>= 1) {
        if (tid < o) red[tid] = fmaxf(red[tid], red[tid + o]);
        __syncthreads();
    }
    m = red[0]; __syncthreads();

    float ev[8];
    float sum = 0.f;
    {
        int j = 0;
        for (int t = s + tid; t < SEQ; t += 256, j++) {
            const float e = expf(row[t] - m);
            ev[j] = e;
            sum += e;
        }
    }
    red[tid] = sum; __syncthreads();
    #pragma unroll
    for (int o = 128; o > 0; o >>= 1) {
        if (tid < o) red[tid] += red[tid + o];
        __syncthreads();
    }
    const float inv = 1.f / red[0];

    for (int t = tid; t < s; t += 256) {
        whi[base + t] = __float2bfloat16(0.f);
        wlo[base + t] = __float2bfloat16(0.f);
    }
    {
        int j = 0;
        for (int t = s + tid; t < SEQ; t += 256, j++) {
            __nv_bfloat16 h, l;
            split2(ev[j] * inv, h, l);
            whi[base + t] = h;
            wlo[base + t] = l;
        }
    }
}

// ---------------------------------------------------------------------------
// Host
// ---------------------------------------------------------------------------
template <typename T>
static T* sym(const void* s) { void* p = nullptr; cudaGetSymbolAddress(&p, s); return (T*)p; }

static void launch_gemm(GP& p, int M, int N, int Z, cudaStream_t st)
{
    dim3 g(N / 256, M / 128, Z);
    tgemm<<<g, 256, GEMM_SMEM, st>>>(p);
}

extern "C" void kernel_launch(void* const* d_in, const int* in_sizes, int n_in,
                              void* d_out, int out_size)
{
    const int*   x   = (const int*)  d_in[0];
    const float* emb = (const float*)d_in[1];
    const float* Wq  = (const float*)d_in[2];
    const float* bq  = (const float*)d_in[3];
    const float* Wk  = (const float*)d_in[4];
    const float* bk  = (const float*)d_in[5];
    const float* Wv  = (const float*)d_in[6];
    const float* bv  = (const float*)d_in[7];
    const float* W1  = (const float*)d_in[8];
    const float* b1  = (const float*)d_in[9];
    const float* W2  = (const float*)d_in[10];
    const float* b2  = (const float*)d_in[11];
    float* out = (float*)d_out;

    // one-time resources (created on the uncaptured correctness call)
    static cudaStream_t s1 = nullptr, s2 = nullptr;
    static cudaEvent_t ev0 = nullptr, evW = nullptr, evV = nullptr, evVT = nullptr;
    if (!s1) {
        cudaFuncSetAttribute(tgemm, cudaFuncAttributeMaxDynamicSharedMemorySize, GEMM_SMEM);
        cudaStreamCreateWithFlags(&s1, cudaStreamNonBlocking);
        cudaStreamCreateWithFlags(&s2, cudaStreamNonBlocking);
        cudaEventCreateWithFlags(&ev0, cudaEventDisableTiming);
        cudaEventCreateWithFlags(&evW, cudaEventDisableTiming);
        cudaEventCreateWithFlags(&evV, cudaEventDisableTiming);
        cudaEventCreateWithFlags(&evVT, cudaEventDisableTiming);
    }

    __nv_bfloat16* hhi = sym<__nv_bfloat16>(g_hhi);
    __nv_bfloat16* hlo = sym<__nv_bfloat16>(g_hlo);
    __nv_bfloat16* qhi = sym<__nv_bfloat16>(g_qhi);
    __nv_bfloat16* qlo = sym<__nv_bfloat16>(g_qlo);
    __nv_bfloat16* khi = sym<__nv_bfloat16>(g_khi);
    __nv_bfloat16* klo = sym<__nv_bfloat16>(g_klo);
    float*         v   = sym<float>(g_v);
    __nv_bfloat16* vthi= sym<__nv_bfloat16>(g_vthi);
    __nv_bfloat16* vtlo= sym<__nv_bfloat16>(g_vtlo);
    float*         sc  = sym<float>(g_sc);
    __nv_bfloat16* whi = sym<__nv_bfloat16>(g_whi);
    __nv_bfloat16* wlo = sym<__nv_bfloat16>(g_wlo);
    __nv_bfloat16* mhi = sym<__nv_bfloat16>(g_mhi);
    __nv_bfloat16* mlo = sym<__nv_bfloat16>(g_mlo);
    __nv_bfloat16* wqt = sym<__nv_bfloat16>(g_wqt);
    __nv_bfloat16* wkt = sym<__nv_bfloat16>(g_wkt);
    __nv_bfloat16* wvt = sym<__nv_bfloat16>(g_wvt);
    __nv_bfloat16* w1t = sym<__nv_bfloat16>(g_w1t);
    __nv_bfloat16* w2t = sym<__nv_bfloat16>(g_w2t);

    const size_t EE = (size_t)EDIM * EDIM;
    const size_t EM = (size_t)EDIM * MDIM;
    const cudaStream_t s0 = 0;

    dim3 tb(32, 8);

    // fork s1: W1/W2 transposes overlap the whole attention phase
    cudaEventRecord(ev0, s0);
    cudaStreamWaitEvent(s1, ev0, 0);
    transpose_split<<<dim3(MDIM/32, EDIM/32, NLAY), tb, 0, s1>>>(W1, w1t, w1t + (size_t)NLAY*EM, EDIM, MDIM, EM, EM);
    transpose_split<<<dim3(EDIM/32, MDIM/32, NLAY), tb, 0, s1>>>(W2, w2t, w2t + (size_t)NLAY*EM, MDIM, EDIM, EM, EM);
    cudaEventRecord(evW, s1);

    // main stream: QKV weight transposes + embedding
    transpose_split<<<dim3(EDIM/32, EDIM/32, 1), tb, 0, s0>>>(Wq, wqt, wqt + EE, EDIM, EDIM, 0, 0);
    transpose_split<<<dim3(EDIM/32, EDIM/32, 1), tb, 0, s0>>>(Wk, wkt, wkt + EE, EDIM, EDIM, 0, 0);
    transpose_split<<<dim3(EDIM/32, EDIM/32, 1), tb, 0, s0>>>(Wv, wvt, wvt + EE, EDIM, EDIM, 0, 0);
    embed_split<<<NROWS, 256, 0, s0>>>(x, emb, hhi, hlo);

    GP p = {};
    p.Ahi = hhi; p.Alo = hlo; p.ldA = EDIM; p.ldB = EDIM; p.ldC = EDIM;
    p.K = EDIM; p.scale = 1.f; p.relu = 0; p.maskSkip = 0; p.triK = 0;
    p.szA = p.szB = p.szC = 0;

    p.Bhi = wqt; p.Blo = wqt + EE; p.bias = bq;
    p.outHi = qhi; p.outLo = qlo; p.outF = nullptr;
    launch_gemm(p, NROWS, EDIM, 1, s0);

    p.Bhi = wkt; p.Blo = wkt + EE; p.bias = bk;
    p.outHi = khi; p.outLo = klo;
    launch_gemm(p, NROWS, EDIM, 1, s0);

    p.Bhi = wvt; p.Blo = wvt + EE; p.bias = bv;
    p.outHi = nullptr; p.outLo = nullptr; p.outF = v;
    launch_gemm(p, NROWS, EDIM, 1, s0);
    cudaEventRecord(evV, s0);

    // fork s2: v transpose overlaps the scores GEMM
    cudaStreamWaitEvent(s2, evV, 0);
    transpose_split<<<dim3(EDIM/32, SEQ/32, BATCH), tb, 0, s2>>>(v, vthi, vtlo, SEQ, EDIM,
                                                                 (size_t)SEQ*EDIM, (size_t)EDIM*SEQ);
    cudaEventRecord(evVT, s2);

    // scores = scale * q k^T  (batched, masked-tile skip)
    p.Ahi = qhi; p.Alo = qlo; p.Bhi = khi; p.Blo = klo;
    p.ldA = EDIM; p.ldB = EDIM; p.ldC = SEQ; p.K = EDIM;
    p.szA = (size_t)SEQ * EDIM; p.szB = (size_t)SEQ * EDIM; p.szC = (size_t)SEQ * SEQ;
    p.bias = nullptr; p.outF = sc; p.outHi = nullptr; p.outLo = nullptr;
    p.scale = 1.f / 32.f; p.relu = 0; p.maskSkip = 1; p.triK = 0;
    launch_gemm(p, SEQ, SEQ, BATCH, s0);

    softmax_split<<<dim3(SEQ, BATCH), 256, 0, s0>>>(sc, whi, wlo);

    // join s2 before w@v
    cudaStreamWaitEvent(s0, evVT, 0);

    // h = relu(w v)  (batched, triangular K skip)
    p.Ahi = whi; p.Alo = wlo; p.Bhi = vthi; p.Blo = vtlo;
    p.ldA = SEQ; p.ldB = SEQ; p.ldC = EDIM; p.K = SEQ;
    p.szA = (size_t)SEQ * SEQ; p.szB = (size_t)EDIM * SEQ; p.szC = (size_t)SEQ * EDIM;
    p.bias = nullptr; p.outF = nullptr; p.outHi = hhi; p.outLo = hlo;
    p.scale = 1.f; p.relu = 1; p.maskSkip = 0; p.triK = 1;
    launch_gemm(p, SEQ, EDIM, BATCH, s0);

    // join s1 before MLP
    cudaStreamWaitEvent(s0, evW, 0);

    // MLP stack
    p.szA = p.szB = p.szC = 0;
    p.maskSkip = 0; p.triK = 0;
    __nv_bfloat16 *curHi = hhi, *curLo = hlo;
    __nv_bfloat16 *altHi = qhi, *altLo = qlo;
    for (int i = 0; i < NLAY; i++) {
        p.Ahi = curHi; p.Alo = curLo;
        p.Bhi = w1t + (size_t)i * EM; p.Blo = w1t + (size_t)(NLAY + i) * EM;
        p.ldA = EDIM; p.ldB = EDIM; p.ldC = MDIM; p.K = EDIM;
        p.bias = b1 + (size_t)i * MDIM;
        p.outHi = mhi; p.outLo = mlo; p.outF = nullptr;
        p.scale = 1.f; p.relu = 1;
        launch_gemm(p, NROWS, MDIM, 1, s0);

        p.Ahi = mhi; p.Alo = mlo;
        p.Bhi = w2t + (size_t)i * EM; p.Blo = w2t + (size_t)(NLAY + i) * EM;
        p.ldA = MDIM; p.ldB = MDIM; p.ldC = EDIM; p.K = MDIM;
        p.bias = b2 + (size_t)i * EDIM;
        if (i == NLAY - 1) {
            p.outHi = nullptr; p.outLo = nullptr; p.outF = out;
        } else {
            p.outHi = altHi; p.outLo = altLo; p.outF = nullptr;
        }
        launch_gemm(p, NROWS, EDIM, 1, s0);

        __nv_bfloat16* t;
        t = curHi; curHi = altHi; altHi = t;
        t = curLo; curLo = altLo; altLo = t;
    }
}